// round 2
// baseline (speedup 1.0000x reference)
#include <cuda_runtime.h>

#define NMAX 100000
#define EMAX 1600000

// ---------------- scratch (static device globals; no allocation) ----------------
__device__ __align__(16) float g_h1[NMAX * 128];   // layer1 GEMM out; reused as layer2 GEMM out
__device__ __align__(16) float g_acc[NMAX * 128];  // layer1 accumulator; then layer1 output (post BN/ReLU)
__device__ __align__(16) float g_as1[NMAX * 4];
__device__ __align__(16) float g_ad1[NMAX * 4];
__device__ __align__(16) float g_m1[NMAX * 4];
__device__ __align__(16) float g_s1[NMAX * 4];
__device__ __align__(16) float g_as2[NMAX];
__device__ __align__(16) float g_ad2[NMAX];
__device__ __align__(16) float g_m2[NMAX];
__device__ __align__(16) float g_s2[NMAX];

#define NEG_SLOPE 0.2f
#define EPS_BN 1e-5f

__device__ __forceinline__ float lrelu(float v) {
    return v > 0.f ? v : NEG_SLOPE * v;
}

// float atomic max via sign-split trick (valid for all non-NaN floats)
__device__ __forceinline__ void atomicMaxF(float* addr, float v) {
    if (v >= 0.f) atomicMax((int*)addr, __float_as_int(v));
    else          atomicMin((unsigned int*)addr, __float_as_uint(v));
}

// ---------------- GEMM: A[n,128] @ W[128,M] -> C[n,M] ----------------
// Tiled: ROWS rows per block, KC=32 k-chunk, each thread 4 rows x 4 cols.
template <int M>
__global__ void gemm_kernel(const float* __restrict__ A,
                            const float* __restrict__ W,
                            float* __restrict__ C, int n) {
    constexpr int KC = 32;
    constexpr int CT = M / 4;        // col-thread groups (128->32, 64->16)
    constexpr int RT = 256 / CT;     // row-thread groups (8 or 16)
    constexpr int ROWS = RT * 4;     // 32 or 64

    __shared__ __align__(16) float xs[ROWS][KC];
    __shared__ __align__(16) float ws[KC][M];

    int tid = threadIdx.x;
    int tc = tid % CT;
    int tr = tid / CT;
    int row0 = blockIdx.x * ROWS;

    float acc[4][4];
#pragma unroll
    for (int i = 0; i < 4; i++)
#pragma unroll
        for (int j = 0; j < 4; j++) acc[i][j] = 0.f;

    for (int k0 = 0; k0 < 128; k0 += KC) {
        for (int i = tid; i < ROWS * KC; i += 256) {
            int r = i / KC, k = i % KC;
            int gr = row0 + r;
            xs[r][k] = (gr < n) ? A[gr * 128 + k0 + k] : 0.f;
        }
        for (int i = tid; i < KC * M; i += 256) {
            int k = i / M, c = i % M;
            ws[k][c] = W[(k0 + k) * M + c];
        }
        __syncthreads();
#pragma unroll
        for (int kk = 0; kk < KC; kk++) {
            float4 wv = *(const float4*)&ws[kk][tc * 4];
            float xv[4];
#pragma unroll
            for (int i = 0; i < 4; i++) xv[i] = xs[tr * 4 + i][kk];
#pragma unroll
            for (int i = 0; i < 4; i++) {
                acc[i][0] += xv[i] * wv.x;
                acc[i][1] += xv[i] * wv.y;
                acc[i][2] += xv[i] * wv.z;
                acc[i][3] += xv[i] * wv.w;
            }
        }
        __syncthreads();
    }
#pragma unroll
    for (int i = 0; i < 4; i++) {
        int gr = row0 + tr * 4 + i;
        if (gr < n) {
            *(float4*)&C[gr * M + tc * 4] =
                make_float4(acc[i][0], acc[i][1], acc[i][2], acc[i][3]);
        }
    }
}

// ---------------- layer 1: attention scores + init ----------------
__global__ void scores1_kernel(const float* __restrict__ att_src,
                               const float* __restrict__ att_dst, int n) {
    int idx = blockIdx.x * blockDim.x + threadIdx.x;
    if (idx >= n * 4) return;
    int node = idx >> 2, h = idx & 3;
    const float* hp = &g_h1[node * 128 + h * 32];
    float s = 0.f, d = 0.f;
#pragma unroll
    for (int j = 0; j < 8; j++) {
        float4 hv = *(const float4*)&hp[j * 4];
        float4 av = *(const float4*)&att_src[h * 32 + j * 4];
        float4 bv = *(const float4*)&att_dst[h * 32 + j * 4];
        s += hv.x * av.x + hv.y * av.y + hv.z * av.z + hv.w * av.w;
        d += hv.x * bv.x + hv.y * bv.y + hv.z * bv.z + hv.w * bv.w;
    }
    g_as1[idx] = s;
    g_ad1[idx] = d;
    g_m1[idx] = __int_as_float(0xff800000);  // -inf
    g_s1[idx] = 0.f;
    float4 z = make_float4(0.f, 0.f, 0.f, 0.f);
    float* ap = &g_acc[node * 128 + h * 32];
#pragma unroll
    for (int j = 0; j < 8; j++) *(float4*)&ap[j * 4] = z;
}

// ---------------- layer 1: per-dst max over edges ----------------
__global__ void edge_max1_kernel(const int* __restrict__ ei, int E, int n) {
    int e = blockIdx.x * blockDim.x + threadIdx.x;
    int ET = E + n;
    if (e >= ET) return;
    int src, dst;
    if (e < E) { src = ei[e]; dst = ei[E + e]; }
    else       { src = e - E; dst = src; }
    float4 a = *(const float4*)&g_as1[src * 4];
    float4 b = *(const float4*)&g_ad1[dst * 4];
    atomicMaxF(&g_m1[dst * 4 + 0], lrelu(a.x + b.x));
    atomicMaxF(&g_m1[dst * 4 + 1], lrelu(a.y + b.y));
    atomicMaxF(&g_m1[dst * 4 + 2], lrelu(a.z + b.z));
    atomicMaxF(&g_m1[dst * 4 + 3], lrelu(a.w + b.w));
}

// ---------------- layer 1: weighted accumulate (warp per edge) ----------------
__global__ void edge_acc1_kernel(const int* __restrict__ ei, int E, int n) {
    long long gtid = (long long)blockIdx.x * blockDim.x + threadIdx.x;
    int e = (int)(gtid >> 5);
    int lane = (int)(gtid & 31);
    int ET = E + n;
    if (e >= ET) return;
    int src, dst;
    if (e < E) { src = ei[e]; dst = ei[E + e]; }
    else       { src = e - E; dst = src; }
    int h = lane >> 3;  // 4 channels per lane -> head = lane/8
    float v = lrelu(g_as1[src * 4 + h] + g_ad1[dst * 4 + h]);
    float p = __expf(v - g_m1[dst * 4 + h]);
    if ((lane & 7) == 0) atomicAdd(&g_s1[dst * 4 + h], p);
    float4 hv = *(const float4*)&g_h1[src * 128 + lane * 4];
    float* op = &g_acc[dst * 128 + lane * 4];
    atomicAdd(op + 0, p * hv.x);
    atomicAdd(op + 1, p * hv.y);
    atomicAdd(op + 2, p * hv.z);
    atomicAdd(op + 3, p * hv.w);
}

// ---------------- layer 1: normalize + bias + BN + ReLU (in place) ----------------
__global__ void finish1_kernel(const float* __restrict__ b1,
                               const float* __restrict__ gamma,
                               const float* __restrict__ beta,
                               const float* __restrict__ mean,
                               const float* __restrict__ var, int n) {
    int idx = blockIdx.x * blockDim.x + threadIdx.x;
    if (idx >= n * 128) return;
    int node = idx >> 7, ch = idx & 127;
    float v = g_acc[idx] / g_s1[node * 4 + (ch >> 5)] + b1[ch];
    v = gamma[ch] * (v - mean[ch]) * rsqrtf(var[ch] + EPS_BN) + beta[ch];
    g_acc[idx] = fmaxf(v, 0.f);
}

// ---------------- layer 2: scores + init + zero d_out ----------------
__global__ void scores2_kernel(const float* __restrict__ att_src,
                               const float* __restrict__ att_dst,
                               float* __restrict__ out, int n) {
    int node = blockIdx.x * blockDim.x + threadIdx.x;
    if (node >= n) return;
    const float* hp = &g_h1[node * 64];
    float s = 0.f, d = 0.f;
#pragma unroll
    for (int j = 0; j < 16; j++) {
        float4 hv = *(const float4*)&hp[j * 4];
        float4 av = *(const float4*)&att_src[j * 4];
        float4 bv = *(const float4*)&att_dst[j * 4];
        s += hv.x * av.x + hv.y * av.y + hv.z * av.z + hv.w * av.w;
        d += hv.x * bv.x + hv.y * bv.y + hv.z * bv.z + hv.w * bv.w;
    }
    g_as2[node] = s;
    g_ad2[node] = d;
    g_m2[node] = __int_as_float(0xff800000);
    g_s2[node] = 0.f;
    float4 z = make_float4(0.f, 0.f, 0.f, 0.f);
#pragma unroll
    for (int j = 0; j < 16; j++) *(float4*)&out[node * 64 + j * 4] = z;
}

__global__ void edge_max2_kernel(const int* __restrict__ ei, int E, int n) {
    int e = blockIdx.x * blockDim.x + threadIdx.x;
    int ET = E + n;
    if (e >= ET) return;
    int src, dst;
    if (e < E) { src = ei[e]; dst = ei[E + e]; }
    else       { src = e - E; dst = src; }
    atomicMaxF(&g_m2[dst], lrelu(g_as2[src] + g_ad2[dst]));
}

__global__ void edge_acc2_kernel(const int* __restrict__ ei,
                                 float* __restrict__ out, int E, int n) {
    long long gtid = (long long)blockIdx.x * blockDim.x + threadIdx.x;
    int e = (int)(gtid >> 5);
    int lane = (int)(gtid & 31);
    int ET = E + n;
    if (e >= ET) return;
    int src, dst;
    if (e < E) { src = ei[e]; dst = ei[E + e]; }
    else       { src = e - E; dst = src; }
    float v = lrelu(g_as2[src] + g_ad2[dst]);
    float p = __expf(v - g_m2[dst]);
    if (lane == 0) atomicAdd(&g_s2[dst], p);
    float2 hv = *(const float2*)&g_h1[src * 64 + lane * 2];
    float* op = &out[dst * 64 + lane * 2];
    atomicAdd(op + 0, p * hv.x);
    atomicAdd(op + 1, p * hv.y);
}

__global__ void finish2_kernel(float* __restrict__ out,
                               const float* __restrict__ b2,
                               const float* __restrict__ gamma,
                               const float* __restrict__ beta,
                               const float* __restrict__ mean,
                               const float* __restrict__ var, int n) {
    int idx = blockIdx.x * blockDim.x + threadIdx.x;
    if (idx >= n * 64) return;
    int node = idx >> 6, c = idx & 63;
    float v = out[idx] / g_s2[node] + b2[c];
    out[idx] = gamma[c] * (v - mean[c]) * rsqrtf(var[c] + EPS_BN) + beta[c];
}

// ---------------- launcher ----------------
extern "C" void kernel_launch(void* const* d_in, const int* in_sizes, int n_in,
                              void* d_out, int out_size) {
    const float* x        = (const float*)d_in[0];
    const int*   ei       = (const int*)d_in[1];   // int32: JAX demotes int64 by default
    const float* W1       = (const float*)d_in[2];
    const float* att_src1 = (const float*)d_in[3];
    const float* att_dst1 = (const float*)d_in[4];
    const float* b1       = (const float*)d_in[5];
    const float* bn1_g    = (const float*)d_in[6];
    const float* bn1_b    = (const float*)d_in[7];
    const float* bn1_m    = (const float*)d_in[8];
    const float* bn1_v    = (const float*)d_in[9];
    const float* W2       = (const float*)d_in[10];
    const float* att_src2 = (const float*)d_in[11];
    const float* att_dst2 = (const float*)d_in[12];
    const float* b2       = (const float*)d_in[13];
    const float* bn2_g    = (const float*)d_in[14];
    const float* bn2_b    = (const float*)d_in[15];
    const float* bn2_m    = (const float*)d_in[16];
    const float* bn2_v    = (const float*)d_in[17];
    float* out = (float*)d_out;

    int n = in_sizes[0] / 128;
    int E = in_sizes[1] / 2;
    int ET = E + n;

    float* h1;
    float* acc;
    cudaGetSymbolAddress((void**)&h1, g_h1);
    cudaGetSymbolAddress((void**)&acc, g_acc);

    const int B = 256;

    // ---- layer 1 ----
    gemm_kernel<128><<<(n + 31) / 32, B>>>(x, W1, h1, n);
    scores1_kernel<<<(n * 4 + B - 1) / B, B>>>(att_src1, att_dst1, n);
    edge_max1_kernel<<<(ET + B - 1) / B, B>>>(ei, E, n);
    {
        long long threads = (long long)ET * 32;
        edge_acc1_kernel<<<(int)((threads + B - 1) / B), B>>>(ei, E, n);
    }
    finish1_kernel<<<(n * 128 + B - 1) / B, B>>>(b1, bn1_g, bn1_b, bn1_m, bn1_v, n);

    // ---- layer 2 ----
    gemm_kernel<64><<<(n + 63) / 64, B>>>(acc, W2, h1, n);
    scores2_kernel<<<(n + B - 1) / B, B>>>(att_src2, att_dst2, out, n);
    edge_max2_kernel<<<(ET + B - 1) / B, B>>>(ei, E, n);
    {
        long long threads = (long long)ET * 32;
        edge_acc2_kernel<<<(int)((threads + B - 1) / B), B>>>(ei, out, E, n);
    }
    finish2_kernel<<<(n * 64 + B - 1) / B, B>>>(out, b2, bn2_g, bn2_b, bn2_m, bn2_v, n);
}

// round 3
// speedup vs baseline: 1.7940x; 1.7940x over previous
#include <cuda_runtime.h>

#define NMAX 100000
#define EMAX 1600000
#define ETMAX (EMAX + NMAX)

// ---------------- scratch (static device globals; no allocation) ----------------
__device__ __align__(16) float g_h1[NMAX * 128];   // layer1 GEMM out; reused as layer2 GEMM out
__device__ __align__(16) float g_acc[NMAX * 128];  // layer1 output (post BN/ReLU)
__device__ __align__(16) float g_as1[NMAX * 4];
__device__ __align__(16) float g_ad1[NMAX * 4];
__device__ __align__(16) float g_as2[NMAX];
__device__ __align__(16) float g_ad2[NMAX];
__device__ int g_cnt[NMAX];
__device__ int g_row[NMAX + 1];
__device__ int g_cur[NMAX];
__device__ int g_csrc[ETMAX];

#define NEG_SLOPE 0.2f
#define EPS_BN 1e-5f

__device__ __forceinline__ float lrelu(float v) {
    return v > 0.f ? v : NEG_SLOPE * v;
}

// ---------------- GEMM: A[n,128] @ W[128,M] -> C[n,M] ----------------
template <int M>
__global__ void gemm_kernel(const float* __restrict__ A,
                            const float* __restrict__ W,
                            float* __restrict__ C, int n) {
    constexpr int KC = 32;
    constexpr int CT = M / 4;
    constexpr int RT = 256 / CT;
    constexpr int ROWS = RT * 4;

    __shared__ __align__(16) float xs[ROWS][KC];
    __shared__ __align__(16) float ws[KC][M];

    int tid = threadIdx.x;
    int tc = tid % CT;
    int tr = tid / CT;
    int row0 = blockIdx.x * ROWS;

    float acc[4][4];
#pragma unroll
    for (int i = 0; i < 4; i++)
#pragma unroll
        for (int j = 0; j < 4; j++) acc[i][j] = 0.f;

    for (int k0 = 0; k0 < 128; k0 += KC) {
        for (int i = tid; i < ROWS * KC; i += 256) {
            int r = i / KC, k = i % KC;
            int gr = row0 + r;
            xs[r][k] = (gr < n) ? A[gr * 128 + k0 + k] : 0.f;
        }
        for (int i = tid; i < KC * M; i += 256) {
            int k = i / M, c = i % M;
            ws[k][c] = W[(k0 + k) * M + c];
        }
        __syncthreads();
#pragma unroll
        for (int kk = 0; kk < KC; kk++) {
            float4 wv = *(const float4*)&ws[kk][tc * 4];
            float xv[4];
#pragma unroll
            for (int i = 0; i < 4; i++) xv[i] = xs[tr * 4 + i][kk];
#pragma unroll
            for (int i = 0; i < 4; i++) {
                acc[i][0] += xv[i] * wv.x;
                acc[i][1] += xv[i] * wv.y;
                acc[i][2] += xv[i] * wv.z;
                acc[i][3] += xv[i] * wv.w;
            }
        }
        __syncthreads();
    }
#pragma unroll
    for (int i = 0; i < 4; i++) {
        int gr = row0 + tr * 4 + i;
        if (gr < n) {
            *(float4*)&C[gr * M + tc * 4] =
                make_float4(acc[i][0], acc[i][1], acc[i][2], acc[i][3]);
        }
    }
}

// ---------------- layer 1: attention scores + zero CSR counters ----------------
__global__ void scores1_kernel(const float* __restrict__ att_src,
                               const float* __restrict__ att_dst, int n) {
    int idx = blockIdx.x * blockDim.x + threadIdx.x;
    if (idx >= n * 4) return;
    int node = idx >> 2, h = idx & 3;
    const float* hp = &g_h1[node * 128 + h * 32];
    float s = 0.f, d = 0.f;
#pragma unroll
    for (int j = 0; j < 8; j++) {
        float4 hv = *(const float4*)&hp[j * 4];
        float4 av = *(const float4*)&att_src[h * 32 + j * 4];
        float4 bv = *(const float4*)&att_dst[h * 32 + j * 4];
        s += hv.x * av.x + hv.y * av.y + hv.z * av.z + hv.w * av.w;
        d += hv.x * bv.x + hv.y * bv.y + hv.z * bv.z + hv.w * bv.w;
    }
    g_as1[idx] = s;
    g_ad1[idx] = d;
    if (h == 0) g_cnt[node] = 0;
}

// ---------------- CSR build: histogram over dst ----------------
__global__ void hist_kernel(const int* __restrict__ ei, int E, int n) {
    int e = blockIdx.x * blockDim.x + threadIdx.x;
    int ET = E + n;
    if (e >= ET) return;
    int dst = (e < E) ? ei[E + e] : (e - E);
    atomicAdd(&g_cnt[dst], 1);
}

// ---------------- CSR build: exclusive scan (single block, 1024 threads) ----------------
__global__ void scan_kernel(int n) {
    __shared__ int s_sums[1024];
    int t = threadIdx.x;
    int C = (n + 1023) / 1024;
    int base = t * C;
    int local = 0;
    for (int i = 0; i < C; i++) {
        int idx = base + i;
        if (idx < n) local += g_cnt[idx];
    }
    s_sums[t] = local;
    __syncthreads();
    for (int off = 1; off < 1024; off <<= 1) {
        int v = 0;
        if (t >= off) v = s_sums[t - off];
        __syncthreads();
        if (t >= off) s_sums[t] += v;
        __syncthreads();
    }
    int running = s_sums[t] - local;  // exclusive prefix
    for (int i = 0; i < C; i++) {
        int idx = base + i;
        if (idx < n) {
            g_row[idx] = running;
            g_cur[idx] = running;
            running += g_cnt[idx];
        }
    }
    if (t == 1023) g_row[n] = s_sums[1023];
}

// ---------------- CSR build: scatter src by dst ----------------
__global__ void scatter_kernel(const int* __restrict__ ei, int E, int n) {
    int e = blockIdx.x * blockDim.x + threadIdx.x;
    int ET = E + n;
    if (e >= ET) return;
    int src, dst;
    if (e < E) { src = ei[e]; dst = ei[E + e]; }
    else       { src = e - E; dst = src; }
    int pos = atomicAdd(&g_cur[dst], 1);
    g_csrc[pos] = src;
}

// ---------------- layer 1: gather per dst (warp/dst) + bias + BN + ReLU ----------------
__global__ void gat1_gather_kernel(const float* __restrict__ b1,
                                   const float* __restrict__ gamma,
                                   const float* __restrict__ beta,
                                   const float* __restrict__ mean,
                                   const float* __restrict__ var, int n) {
    int w = (blockIdx.x * blockDim.x + threadIdx.x) >> 5;
    int lane = threadIdx.x & 31;
    if (w >= n) return;
    int h = lane >> 3;
    int beg = g_row[w], end = g_row[w + 1];
    float ad = g_ad1[w * 4 + h];

    // per-head max (8 lanes per head, strided over edges)
    float m = __int_as_float(0xff800000);
    for (int e = beg + (lane & 7); e < end; e += 8) {
        int s = g_csrc[e];
        m = fmaxf(m, lrelu(g_as1[s * 4 + h] + ad));
    }
    m = fmaxf(m, __shfl_xor_sync(0xffffffffu, m, 1));
    m = fmaxf(m, __shfl_xor_sync(0xffffffffu, m, 2));
    m = fmaxf(m, __shfl_xor_sync(0xffffffffu, m, 4));

    // accumulate
    float4 acc = make_float4(0.f, 0.f, 0.f, 0.f);
    float ssum = 0.f;
    for (int e0 = beg; e0 < end; e0 += 32) {
        int e = e0 + lane;
        int sl = (e < end) ? g_csrc[e] : 0;
        int cnt = min(32, end - e0);
        for (int j = 0; j < cnt; j++) {
            int sj = __shfl_sync(0xffffffffu, sl, j);
            float p = __expf(lrelu(g_as1[sj * 4 + h] + ad) - m);
            ssum += p;
            float4 hv = *(const float4*)&g_h1[sj * 128 + lane * 4];
            acc.x += p * hv.x;
            acc.y += p * hv.y;
            acc.z += p * hv.z;
            acc.w += p * hv.w;
        }
    }

    // finish: normalize + bias + BN + ReLU
    int ch = lane * 4;
    float inv = 1.f / ssum;
    float4 o;
    float* op = &g_acc[w * 128 + ch];
#pragma unroll
    for (int j = 0; j < 4; j++) {
        float v = ((&acc.x)[j]) * inv + b1[ch + j];
        v = gamma[ch + j] * (v - mean[ch + j]) * rsqrtf(var[ch + j] + EPS_BN) + beta[ch + j];
        (&o.x)[j] = fmaxf(v, 0.f);
    }
    *(float4*)op = o;
}

// ---------------- layer 2: scores ----------------
__global__ void scores2_kernel(const float* __restrict__ att_src,
                               const float* __restrict__ att_dst, int n) {
    int node = blockIdx.x * blockDim.x + threadIdx.x;
    if (node >= n) return;
    const float* hp = &g_h1[node * 64];
    float s = 0.f, d = 0.f;
#pragma unroll
    for (int j = 0; j < 16; j++) {
        float4 hv = *(const float4*)&hp[j * 4];
        float4 av = *(const float4*)&att_src[j * 4];
        float4 bv = *(const float4*)&att_dst[j * 4];
        s += hv.x * av.x + hv.y * av.y + hv.z * av.z + hv.w * av.w;
        d += hv.x * bv.x + hv.y * bv.y + hv.z * bv.z + hv.w * bv.w;
    }
    g_as2[node] = s;
    g_ad2[node] = d;
}

// ---------------- layer 2: gather per dst (warp/dst) + bias + BN ----------------
__global__ void gat2_gather_kernel(float* __restrict__ out,
                                   const float* __restrict__ b2,
                                   const float* __restrict__ gamma,
                                   const float* __restrict__ beta,
                                   const float* __restrict__ mean,
                                   const float* __restrict__ var, int n) {
    int w = (blockIdx.x * blockDim.x + threadIdx.x) >> 5;
    int lane = threadIdx.x & 31;
    if (w >= n) return;
    int beg = g_row[w], end = g_row[w + 1];
    float ad = g_ad2[w];

    float m = __int_as_float(0xff800000);
    for (int e = beg + lane; e < end; e += 32) {
        int s = g_csrc[e];
        m = fmaxf(m, lrelu(g_as2[s] + ad));
    }
#pragma unroll
    for (int off = 16; off > 0; off >>= 1)
        m = fmaxf(m, __shfl_xor_sync(0xffffffffu, m, off));

    float2 acc = make_float2(0.f, 0.f);
    float ssum = 0.f;
    for (int e0 = beg; e0 < end; e0 += 32) {
        int e = e0 + lane;
        int sl = (e < end) ? g_csrc[e] : 0;
        int cnt = min(32, end - e0);
        for (int j = 0; j < cnt; j++) {
            int sj = __shfl_sync(0xffffffffu, sl, j);
            float p = __expf(lrelu(g_as2[sj] + ad) - m);
            ssum += p;
            float2 hv = *(const float2*)&g_h1[sj * 64 + lane * 2];
            acc.x += p * hv.x;
            acc.y += p * hv.y;
        }
    }

    int ch = lane * 2;
    float inv = 1.f / ssum;
    float vx = acc.x * inv + b2[ch];
    float vy = acc.y * inv + b2[ch + 1];
    vx = gamma[ch] * (vx - mean[ch]) * rsqrtf(var[ch] + EPS_BN) + beta[ch];
    vy = gamma[ch + 1] * (vy - mean[ch + 1]) * rsqrtf(var[ch + 1] + EPS_BN) + beta[ch + 1];
    *(float2*)&out[w * 64 + ch] = make_float2(vx, vy);
}

// ---------------- launcher ----------------
extern "C" void kernel_launch(void* const* d_in, const int* in_sizes, int n_in,
                              void* d_out, int out_size) {
    const float* x        = (const float*)d_in[0];
    const int*   ei       = (const int*)d_in[1];   // int32 (JAX demotes int64)
    const float* W1       = (const float*)d_in[2];
    const float* att_src1 = (const float*)d_in[3];
    const float* att_dst1 = (const float*)d_in[4];
    const float* b1       = (const float*)d_in[5];
    const float* bn1_g    = (const float*)d_in[6];
    const float* bn1_b    = (const float*)d_in[7];
    const float* bn1_m    = (const float*)d_in[8];
    const float* bn1_v    = (const float*)d_in[9];
    const float* W2       = (const float*)d_in[10];
    const float* att_src2 = (const float*)d_in[11];
    const float* att_dst2 = (const float*)d_in[12];
    const float* b2       = (const float*)d_in[13];
    const float* bn2_g    = (const float*)d_in[14];
    const float* bn2_b    = (const float*)d_in[15];
    const float* bn2_m    = (const float*)d_in[16];
    const float* bn2_v    = (const float*)d_in[17];
    float* out = (float*)d_out;

    int n = in_sizes[0] / 128;
    int E = in_sizes[1] / 2;
    int ET = E + n;

    float* h1;
    float* acc;
    cudaGetSymbolAddress((void**)&h1, g_h1);
    cudaGetSymbolAddress((void**)&acc, g_acc);

    const int B = 256;

    // ---- layer 1 GEMM + scores (also zeroes CSR counters) ----
    gemm_kernel<128><<<(n + 31) / 32, B>>>(x, W1, h1, n);
    scores1_kernel<<<(n * 4 + B - 1) / B, B>>>(att_src1, att_dst1, n);

    // ---- CSR build (dst-sorted src lists, includes self-loops) ----
    hist_kernel<<<(ET + B - 1) / B, B>>>(ei, E, n);
    scan_kernel<<<1, 1024>>>(n);
    scatter_kernel<<<(ET + B - 1) / B, B>>>(ei, E, n);

    // ---- layer 1 gather (softmax + aggregate + bias + BN + ReLU) ----
    gat1_gather_kernel<<<(n * 32 + B - 1) / B, B>>>(b1, bn1_g, bn1_b, bn1_m, bn1_v, n);

    // ---- layer 2 ----
    gemm_kernel<64><<<(n + 63) / 64, B>>>(acc, W2, h1, n);
    scores2_kernel<<<(n + B - 1) / B, B>>>(att_src2, att_dst2, n);
    gat2_gather_kernel<<<(n * 32 + B - 1) / B, B>>>(out, b2, bn2_g, bn2_b, bn2_m, bn2_v, n);
}

// round 4
// speedup vs baseline: 2.4802x; 1.3826x over previous
#include <cuda_runtime.h>

#define NMAX 100000
#define EMAX 1600000
#define ETMAX (EMAX + NMAX)
#define SCAN_CHUNK 1024
#define SCAN_BLOCKS ((NMAX + SCAN_CHUNK - 1) / SCAN_CHUNK)

// ---------------- scratch (static device globals; no allocation) ----------------
__device__ __align__(16) float g_h1[NMAX * 128];   // layer1 GEMM out; reused as layer2 GEMM out
__device__ __align__(16) float g_acc[NMAX * 128];  // layer1 output (post BN/ReLU)
__device__ __align__(16) float g_as1[NMAX * 4];
__device__ __align__(16) float g_ad1[NMAX * 4];
__device__ __align__(16) float g_as2[NMAX];
__device__ __align__(16) float g_ad2[NMAX];
__device__ int g_cnt[NMAX];
__device__ int g_row[NMAX + 1];
__device__ int g_cur[NMAX];
__device__ int g_csrc[ETMAX];
__device__ int g_part[SCAN_BLOCKS + 1];

#define NEG_SLOPE 0.2f
#define EPS_BN 1e-5f

__device__ __forceinline__ float lrelu(float v) {
    return v > 0.f ? v : NEG_SLOPE * v;
}

// ---------------- GEMM: A[n,128] @ W[128,M] -> C[n,M] ----------------
template <int M>
__global__ void gemm_kernel(const float* __restrict__ A,
                            const float* __restrict__ W,
                            float* __restrict__ C, int n) {
    constexpr int KC = 32;
    constexpr int CT = M / 4;
    constexpr int RT = 256 / CT;
    constexpr int ROWS = RT * 4;

    __shared__ __align__(16) float xs[ROWS][KC];
    __shared__ __align__(16) float ws[KC][M];

    int tid = threadIdx.x;
    int tc = tid % CT;
    int tr = tid / CT;
    int row0 = blockIdx.x * ROWS;

    float acc[4][4];
#pragma unroll
    for (int i = 0; i < 4; i++)
#pragma unroll
        for (int j = 0; j < 4; j++) acc[i][j] = 0.f;

    for (int k0 = 0; k0 < 128; k0 += KC) {
        for (int i = tid; i < ROWS * KC; i += 256) {
            int r = i / KC, k = i % KC;
            int gr = row0 + r;
            xs[r][k] = (gr < n) ? A[gr * 128 + k0 + k] : 0.f;
        }
        for (int i = tid; i < KC * M; i += 256) {
            int k = i / M, c = i % M;
            ws[k][c] = W[(k0 + k) * M + c];
        }
        __syncthreads();
#pragma unroll
        for (int kk = 0; kk < KC; kk++) {
            float4 wv = *(const float4*)&ws[kk][tc * 4];
            float xv[4];
#pragma unroll
            for (int i = 0; i < 4; i++) xv[i] = xs[tr * 4 + i][kk];
#pragma unroll
            for (int i = 0; i < 4; i++) {
                acc[i][0] += xv[i] * wv.x;
                acc[i][1] += xv[i] * wv.y;
                acc[i][2] += xv[i] * wv.z;
                acc[i][3] += xv[i] * wv.w;
            }
        }
        __syncthreads();
    }
#pragma unroll
    for (int i = 0; i < 4; i++) {
        int gr = row0 + tr * 4 + i;
        if (gr < n) {
            *(float4*)&C[gr * M + tc * 4] =
                make_float4(acc[i][0], acc[i][1], acc[i][2], acc[i][3]);
        }
    }
}

// ---------------- layer 1: attention scores + zero CSR counters ----------------
__global__ void scores1_kernel(const float* __restrict__ att_src,
                               const float* __restrict__ att_dst, int n) {
    int idx = blockIdx.x * blockDim.x + threadIdx.x;
    if (idx >= n * 4) return;
    int node = idx >> 2, h = idx & 3;
    const float* hp = &g_h1[node * 128 + h * 32];
    float s = 0.f, d = 0.f;
#pragma unroll
    for (int j = 0; j < 8; j++) {
        float4 hv = *(const float4*)&hp[j * 4];
        float4 av = *(const float4*)&att_src[h * 32 + j * 4];
        float4 bv = *(const float4*)&att_dst[h * 32 + j * 4];
        s += hv.x * av.x + hv.y * av.y + hv.z * av.z + hv.w * av.w;
        d += hv.x * bv.x + hv.y * bv.y + hv.z * bv.z + hv.w * bv.w;
    }
    g_as1[idx] = s;
    g_ad1[idx] = d;
    if (h == 0) g_cnt[node] = 0;
}

// ---------------- CSR build: histogram over dst ----------------
__global__ void hist_kernel(const int* __restrict__ ei, int E, int n) {
    int e = blockIdx.x * blockDim.x + threadIdx.x;
    int ET = E + n;
    if (e >= ET) return;
    int dst = (e < E) ? ei[E + e] : (e - E);
    atomicAdd(&g_cnt[dst], 1);
}

// ---------------- CSR build: two-level parallel exclusive scan ----------------
// Level 1: per-block partial sums over SCAN_CHUNK elements (256 threads x 4)
__global__ void scan_part_kernel(int n) {
    __shared__ int sh[256];
    int blk = blockIdx.x;
    int t = threadIdx.x;
    int base = blk * SCAN_CHUNK + t * 4;
    int s = 0;
#pragma unroll
    for (int i = 0; i < 4; i++) {
        int idx = base + i;
        if (idx < n) s += g_cnt[idx];
    }
    sh[t] = s;
    __syncthreads();
#pragma unroll
    for (int off = 128; off > 0; off >>= 1) {
        if (t < off) sh[t] += sh[t + off];
        __syncthreads();
    }
    if (t == 0) g_part[blk] = sh[0];
}

// Level 2: scan the partials (single small block)
__global__ void scan_top_kernel(int nb, int n) {
    __shared__ int sh[SCAN_BLOCKS];
    int t = threadIdx.x;
    int v = (t < nb) ? g_part[t] : 0;
    sh[t] = v;
    __syncthreads();
    for (int off = 1; off < SCAN_BLOCKS; off <<= 1) {
        int u = (t >= off) ? sh[t - off] : 0;
        __syncthreads();
        sh[t] += u;
        __syncthreads();
    }
    if (t < nb) g_part[t] = sh[t] - v;  // exclusive
    if (t == nb - 1) g_row[n] = sh[t];  // total
}

// Level 3: block-local exclusive scan + block offset -> g_row / g_cur
__global__ void scan_down_kernel(int n) {
    __shared__ int sh[256];
    int blk = blockIdx.x;
    int t = threadIdx.x;
    int base = blk * SCAN_CHUNK + t * 4;
    int v[4];
    int s = 0;
#pragma unroll
    for (int i = 0; i < 4; i++) {
        int idx = base + i;
        v[i] = (idx < n) ? g_cnt[idx] : 0;
        s += v[i];
    }
    sh[t] = s;
    __syncthreads();
    for (int off = 1; off < 256; off <<= 1) {
        int u = (t >= off) ? sh[t - off] : 0;
        __syncthreads();
        sh[t] += u;
        __syncthreads();
    }
    int running = sh[t] - s + g_part[blk];  // exclusive prefix for this thread
#pragma unroll
    for (int i = 0; i < 4; i++) {
        int idx = base + i;
        if (idx < n) {
            g_row[idx] = running;
            g_cur[idx] = running;
            running += v[i];
        }
    }
}

// ---------------- CSR build: scatter src by dst ----------------
__global__ void scatter_kernel(const int* __restrict__ ei, int E, int n) {
    int e = blockIdx.x * blockDim.x + threadIdx.x;
    int ET = E + n;
    if (e >= ET) return;
    int src, dst;
    if (e < E) { src = ei[e]; dst = ei[E + e]; }
    else       { src = e - E; dst = src; }
    int pos = atomicAdd(&g_cur[dst], 1);
    g_csrc[pos] = src;
}

// ---------------- layer 1: gather per dst (warp/dst) + bias + BN + ReLU ----------------
__global__ void gat1_gather_kernel(const float* __restrict__ b1,
                                   const float* __restrict__ gamma,
                                   const float* __restrict__ beta,
                                   const float* __restrict__ mean,
                                   const float* __restrict__ var, int n) {
    int w = (blockIdx.x * blockDim.x + threadIdx.x) >> 5;
    int lane = threadIdx.x & 31;
    if (w >= n) return;
    int h = lane >> 3;
    int beg = g_row[w], end = g_row[w + 1];
    float ad = g_ad1[w * 4 + h];

    // per-head max (8 lanes per head, strided over edges)
    float m = __int_as_float(0xff800000);
    for (int e = beg + (lane & 7); e < end; e += 8) {
        int s = g_csrc[e];
        m = fmaxf(m, lrelu(g_as1[s * 4 + h] + ad));
    }
    m = fmaxf(m, __shfl_xor_sync(0xffffffffu, m, 1));
    m = fmaxf(m, __shfl_xor_sync(0xffffffffu, m, 2));
    m = fmaxf(m, __shfl_xor_sync(0xffffffffu, m, 4));

    // accumulate
    float4 acc = make_float4(0.f, 0.f, 0.f, 0.f);
    float ssum = 0.f;
    for (int e0 = beg; e0 < end; e0 += 32) {
        int e = e0 + lane;
        int sl = (e < end) ? g_csrc[e] : 0;
        int cnt = min(32, end - e0);
        for (int j = 0; j < cnt; j++) {
            int sj = __shfl_sync(0xffffffffu, sl, j);
            float p = __expf(lrelu(g_as1[sj * 4 + h] + ad) - m);
            ssum += p;
            float4 hv = *(const float4*)&g_h1[sj * 128 + lane * 4];
            acc.x += p * hv.x;
            acc.y += p * hv.y;
            acc.z += p * hv.z;
            acc.w += p * hv.w;
        }
    }

    // finish: normalize + bias + BN + ReLU
    int ch = lane * 4;
    float inv = 1.f / ssum;
    float4 o;
    float* op = &g_acc[w * 128 + ch];
#pragma unroll
    for (int j = 0; j < 4; j++) {
        float v = ((&acc.x)[j]) * inv + b1[ch + j];
        v = gamma[ch + j] * (v - mean[ch + j]) * rsqrtf(var[ch + j] + EPS_BN) + beta[ch + j];
        (&o.x)[j] = fmaxf(v, 0.f);
    }
    *(float4*)op = o;
}

// ---------------- layer 2: scores ----------------
__global__ void scores2_kernel(const float* __restrict__ att_src,
                               const float* __restrict__ att_dst, int n) {
    int node = blockIdx.x * blockDim.x + threadIdx.x;
    if (node >= n) return;
    const float* hp = &g_h1[node * 64];
    float s = 0.f, d = 0.f;
#pragma unroll
    for (int j = 0; j < 16; j++) {
        float4 hv = *(const float4*)&hp[j * 4];
        float4 av = *(const float4*)&att_src[j * 4];
        float4 bv = *(const float4*)&att_dst[j * 4];
        s += hv.x * av.x + hv.y * av.y + hv.z * av.z + hv.w * av.w;
        d += hv.x * bv.x + hv.y * bv.y + hv.z * bv.z + hv.w * bv.w;
    }
    g_as2[node] = s;
    g_ad2[node] = d;
}

// ---------------- layer 2: gather per dst (warp/dst) + bias + BN ----------------
__global__ void gat2_gather_kernel(float* __restrict__ out,
                                   const float* __restrict__ b2,
                                   const float* __restrict__ gamma,
                                   const float* __restrict__ beta,
                                   const float* __restrict__ mean,
                                   const float* __restrict__ var, int n) {
    int w = (blockIdx.x * blockDim.x + threadIdx.x) >> 5;
    int lane = threadIdx.x & 31;
    if (w >= n) return;
    int beg = g_row[w], end = g_row[w + 1];
    float ad = g_ad2[w];

    float m = __int_as_float(0xff800000);
    for (int e = beg + lane; e < end; e += 32) {
        int s = g_csrc[e];
        m = fmaxf(m, lrelu(g_as2[s] + ad));
    }
#pragma unroll
    for (int off = 16; off > 0; off >>= 1)
        m = fmaxf(m, __shfl_xor_sync(0xffffffffu, m, off));

    float2 acc = make_float2(0.f, 0.f);
    float ssum = 0.f;
    for (int e0 = beg; e0 < end; e0 += 32) {
        int e = e0 + lane;
        int sl = (e < end) ? g_csrc[e] : 0;
        int cnt = min(32, end - e0);
        for (int j = 0; j < cnt; j++) {
            int sj = __shfl_sync(0xffffffffu, sl, j);
            float p = __expf(lrelu(g_as2[sj] + ad) - m);
            ssum += p;
            float2 hv = *(const float2*)&g_h1[sj * 64 + lane * 2];
            acc.x += p * hv.x;
            acc.y += p * hv.y;
        }
    }

    int ch = lane * 2;
    float inv = 1.f / ssum;
    float vx = acc.x * inv + b2[ch];
    float vy = acc.y * inv + b2[ch + 1];
    vx = gamma[ch] * (vx - mean[ch]) * rsqrtf(var[ch] + EPS_BN) + beta[ch];
    vy = gamma[ch + 1] * (vy - mean[ch + 1]) * rsqrtf(var[ch + 1] + EPS_BN) + beta[ch + 1];
    *(float2*)&out[w * 64 + ch] = make_float2(vx, vy);
}

// ---------------- launcher ----------------
extern "C" void kernel_launch(void* const* d_in, const int* in_sizes, int n_in,
                              void* d_out, int out_size) {
    const float* x        = (const float*)d_in[0];
    const int*   ei       = (const int*)d_in[1];   // int32 (JAX demotes int64)
    const float* W1       = (const float*)d_in[2];
    const float* att_src1 = (const float*)d_in[3];
    const float* att_dst1 = (const float*)d_in[4];
    const float* b1       = (const float*)d_in[5];
    const float* bn1_g    = (const float*)d_in[6];
    const float* bn1_b    = (const float*)d_in[7];
    const float* bn1_m    = (const float*)d_in[8];
    const float* bn1_v    = (const float*)d_in[9];
    const float* W2       = (const float*)d_in[10];
    const float* att_src2 = (const float*)d_in[11];
    const float* att_dst2 = (const float*)d_in[12];
    const float* b2       = (const float*)d_in[13];
    const float* bn2_g    = (const float*)d_in[14];
    const float* bn2_b    = (const float*)d_in[15];
    const float* bn2_m    = (const float*)d_in[16];
    const float* bn2_v    = (const float*)d_in[17];
    float* out = (float*)d_out;

    int n = in_sizes[0] / 128;
    int E = in_sizes[1] / 2;
    int ET = E + n;
    int nb = (n + SCAN_CHUNK - 1) / SCAN_CHUNK;

    float* h1;
    float* acc;
    cudaGetSymbolAddress((void**)&h1, g_h1);
    cudaGetSymbolAddress((void**)&acc, g_acc);

    const int B = 256;

    // ---- layer 1 GEMM + scores (also zeroes CSR counters) ----
    gemm_kernel<128><<<(n + 31) / 32, B>>>(x, W1, h1, n);
    scores1_kernel<<<(n * 4 + B - 1) / B, B>>>(att_src1, att_dst1, n);

    // ---- CSR build (dst-sorted src lists, includes self-loops) ----
    hist_kernel<<<(ET + B - 1) / B, B>>>(ei, E, n);
    scan_part_kernel<<<nb, 256>>>(n);
    scan_top_kernel<<<1, SCAN_BLOCKS>>>(nb, n);
    scan_down_kernel<<<nb, 256>>>(n);
    scatter_kernel<<<(ET + B - 1) / B, B>>>(ei, E, n);

    // ---- layer 1 gather (softmax + aggregate + bias + BN + ReLU) ----
    gat1_gather_kernel<<<(n * 32 + B - 1) / B, B>>>(b1, bn1_g, bn1_b, bn1_m, bn1_v, n);

    // ---- layer 2 ----
    gemm_kernel<64><<<(n + 63) / 64, B>>>(acc, W2, h1, n);
    scores2_kernel<<<(n + B - 1) / B, B>>>(att_src2, att_dst2, n);
    gat2_gather_kernel<<<(n * 32 + B - 1) / B, B>>>(out, b2, bn2_g, bn2_b, bn2_m, bn2_v, n);
}

// round 5
// speedup vs baseline: 2.8845x; 1.1630x over previous
#include <cuda_runtime.h>

#define NMAX 100000
#define EMAX 1600000
#define ETMAX (EMAX + NMAX)
#define SCAN_CHUNK 1024
#define SCAN_BLOCKS ((NMAX + SCAN_CHUNK - 1) / SCAN_CHUNK)

// ---------------- scratch (static device globals; no allocation) ----------------
__device__ __align__(16) float g_h1[NMAX * 128];   // layer1 GEMM out; reused as layer2 GEMM out
__device__ __align__(16) float g_acc[NMAX * 128];  // layer1 output (post BN/ReLU)
__device__ __align__(16) float g_as1[NMAX * 4];
__device__ __align__(16) float g_ad1[NMAX * 4];
__device__ __align__(16) float g_as2[NMAX];
__device__ __align__(16) float g_ad2[NMAX];
__device__ int g_cnt[NMAX];
__device__ int g_row[NMAX + 1];
__device__ int g_cur[NMAX];
__device__ int g_csrc[ETMAX];
__device__ int g_part[SCAN_BLOCKS + 1];

#define NEG_SLOPE 0.2f
#define EPS_BN 1e-5f

__device__ __forceinline__ float lrelu(float v) {
    return v > 0.f ? v : NEG_SLOPE * v;
}

// ---------------- fused GEMM + attention scores ----------------
// C[n,BN] = A[n,128] @ W[128,BN]; 8x8 register tile per thread, BK=16.
// FUSE==1: also write g_as1/g_ad1 (4 heads x 32ch) and zero g_cnt.
// FUSE==2: also write g_as2/g_ad2 (1 head x 64ch).
template <int BM, int BN, int FUSE>
__global__ void __launch_bounds__(256) gemm_fused_kernel(
    const float* __restrict__ A, const float* __restrict__ W,
    float* __restrict__ C,
    const float* __restrict__ att_s, const float* __restrict__ att_d, int n) {
    constexpr int BK = 16;
    constexpr int TX = BN / 8;            // 16 (BN=128) or 8 (BN=64)
    constexpr int NT = (BM / 8) * TX;     // 256 both configs

    __shared__ __align__(16) float xs[BK][BM + 4];  // transposed A tile (+4 pad)
    __shared__ __align__(16) float ws[BK][BN];

    int tid = threadIdx.x;
    int tx = tid % TX;
    int ty = tid / TX;
    int row0 = blockIdx.x * BM;

    float acc[8][8];
#pragma unroll
    for (int i = 0; i < 8; i++)
#pragma unroll
        for (int j = 0; j < 8; j++) acc[i][j] = 0.f;

    for (int k0 = 0; k0 < 128; k0 += BK) {
        __syncthreads();
        // load A tile (BM x 16) -> xs transposed
#pragma unroll
        for (int rep = 0; rep < BM / 64; rep++) {
            int i = tid + rep * NT;       // float4 index in [0, BM*4)
            int r = i >> 2, c4 = i & 3;
            int gr = row0 + r;
            float4 v = make_float4(0.f, 0.f, 0.f, 0.f);
            if (gr < n) v = *(const float4*)&A[gr * 128 + k0 + c4 * 4];
            xs[c4 * 4 + 0][r] = v.x;
            xs[c4 * 4 + 1][r] = v.y;
            xs[c4 * 4 + 2][r] = v.z;
            xs[c4 * 4 + 3][r] = v.w;
        }
        // load W tile (16 x BN), fully coalesced
#pragma unroll
        for (int rep = 0; rep < (BK * BN / 4) / NT; rep++) {
            int i = tid + rep * NT;
            int kr = i / (BN / 4), c4 = i % (BN / 4);
            *(float4*)&ws[kr][c4 * 4] = *(const float4*)&W[(k0 + kr) * BN + c4 * 4];
        }
        __syncthreads();
#pragma unroll
        for (int kk = 0; kk < BK; kk++) {
            float a[8], b[8];
            *(float4*)&a[0] = *(const float4*)&xs[kk][ty * 8];
            *(float4*)&a[4] = *(const float4*)&xs[kk][ty * 8 + 4];
            *(float4*)&b[0] = *(const float4*)&ws[kk][tx * 8];
            *(float4*)&b[4] = *(const float4*)&ws[kk][tx * 8 + 4];
#pragma unroll
            for (int i = 0; i < 8; i++)
#pragma unroll
                for (int j = 0; j < 8; j++) acc[i][j] += a[i] * b[j];
        }
    }

    // store C
#pragma unroll
    for (int i = 0; i < 8; i++) {
        int gr = row0 + ty * 8 + i;
        if (gr < n) {
            *(float4*)&C[gr * BN + tx * 8] =
                make_float4(acc[i][0], acc[i][1], acc[i][2], acc[i][3]);
            *(float4*)&C[gr * BN + tx * 8 + 4] =
                make_float4(acc[i][4], acc[i][5], acc[i][6], acc[i][7]);
        }
    }

    // fused attention scores
    float as_r[8], ad_r[8];
#pragma unroll
    for (int j = 0; j < 8; j++) {
        as_r[j] = att_s[tx * 8 + j];
        ad_r[j] = att_d[tx * 8 + j];
    }
    float sa[8], sd[8];
#pragma unroll
    for (int i = 0; i < 8; i++) {
        float s = 0.f, d = 0.f;
#pragma unroll
        for (int j = 0; j < 8; j++) {
            s += acc[i][j] * as_r[j];
            d += acc[i][j] * ad_r[j];
        }
        sa[i] = s;
        sd[i] = d;
    }
    if (FUSE == 1) {
        // head = tx/4; reduce over 4 consecutive lanes (tx%4 group)
#pragma unroll
        for (int i = 0; i < 8; i++) {
            sa[i] += __shfl_xor_sync(0xffffffffu, sa[i], 1);
            sa[i] += __shfl_xor_sync(0xffffffffu, sa[i], 2);
            sd[i] += __shfl_xor_sync(0xffffffffu, sd[i], 1);
            sd[i] += __shfl_xor_sync(0xffffffffu, sd[i], 2);
        }
        if ((tx & 3) == 0) {
            int h = tx >> 2;
#pragma unroll
            for (int i = 0; i < 8; i++) {
                int gr = row0 + ty * 8 + i;
                if (gr < n) {
                    g_as1[gr * 4 + h] = sa[i];
                    g_ad1[gr * 4 + h] = sd[i];
                }
            }
        }
        // zero CSR counters for this block's rows
        if (tid < BM) {
            int gr = row0 + tid;
            if (gr < n) g_cnt[gr] = 0;
        }
    } else {
        // single head: reduce over all 8 tx lanes
#pragma unroll
        for (int i = 0; i < 8; i++) {
            sa[i] += __shfl_xor_sync(0xffffffffu, sa[i], 1);
            sa[i] += __shfl_xor_sync(0xffffffffu, sa[i], 2);
            sa[i] += __shfl_xor_sync(0xffffffffu, sa[i], 4);
            sd[i] += __shfl_xor_sync(0xffffffffu, sd[i], 1);
            sd[i] += __shfl_xor_sync(0xffffffffu, sd[i], 2);
            sd[i] += __shfl_xor_sync(0xffffffffu, sd[i], 4);
        }
        if (tx == 0) {
#pragma unroll
            for (int i = 0; i < 8; i++) {
                int gr = row0 + ty * 8 + i;
                if (gr < n) {
                    g_as2[gr] = sa[i];
                    g_ad2[gr] = sd[i];
                }
            }
        }
    }
}

// ---------------- CSR build: histogram over dst ----------------
__global__ void hist_kernel(const int* __restrict__ ei, int E, int n) {
    int e = blockIdx.x * blockDim.x + threadIdx.x;
    int ET = E + n;
    if (e >= ET) return;
    int dst = (e < E) ? ei[E + e] : (e - E);
    atomicAdd(&g_cnt[dst], 1);
}

// ---------------- CSR build: two-level parallel exclusive scan ----------------
__global__ void scan_part_kernel(int n) {
    __shared__ int sh[256];
    int blk = blockIdx.x;
    int t = threadIdx.x;
    int base = blk * SCAN_CHUNK + t * 4;
    int s = 0;
#pragma unroll
    for (int i = 0; i < 4; i++) {
        int idx = base + i;
        if (idx < n) s += g_cnt[idx];
    }
    sh[t] = s;
    __syncthreads();
#pragma unroll
    for (int off = 128; off > 0; off >>= 1) {
        if (t < off) sh[t] += sh[t + off];
        __syncthreads();
    }
    if (t == 0) g_part[blk] = sh[0];
}

__global__ void scan_top_kernel(int nb, int n) {
    __shared__ int sh[SCAN_BLOCKS];
    int t = threadIdx.x;
    int v = (t < nb) ? g_part[t] : 0;
    sh[t] = v;
    __syncthreads();
    for (int off = 1; off < SCAN_BLOCKS; off <<= 1) {
        int u = (t >= off) ? sh[t - off] : 0;
        __syncthreads();
        sh[t] += u;
        __syncthreads();
    }
    if (t < nb) g_part[t] = sh[t] - v;  // exclusive
    if (t == nb - 1) g_row[n] = sh[t];  // total
}

__global__ void scan_down_kernel(int n) {
    __shared__ int sh[256];
    int blk = blockIdx.x;
    int t = threadIdx.x;
    int base = blk * SCAN_CHUNK + t * 4;
    int v[4];
    int s = 0;
#pragma unroll
    for (int i = 0; i < 4; i++) {
        int idx = base + i;
        v[i] = (idx < n) ? g_cnt[idx] : 0;
        s += v[i];
    }
    sh[t] = s;
    __syncthreads();
    for (int off = 1; off < 256; off <<= 1) {
        int u = (t >= off) ? sh[t - off] : 0;
        __syncthreads();
        sh[t] += u;
        __syncthreads();
    }
    int running = sh[t] - s + g_part[blk];
#pragma unroll
    for (int i = 0; i < 4; i++) {
        int idx = base + i;
        if (idx < n) {
            g_row[idx] = running;
            g_cur[idx] = running;
            running += v[i];
        }
    }
}

// ---------------- CSR build: scatter src by dst ----------------
__global__ void scatter_kernel(const int* __restrict__ ei, int E, int n) {
    int e = blockIdx.x * blockDim.x + threadIdx.x;
    int ET = E + n;
    if (e >= ET) return;
    int src, dst;
    if (e < E) { src = ei[e]; dst = ei[E + e]; }
    else       { src = e - E; dst = src; }
    int pos = atomicAdd(&g_cur[dst], 1);
    g_csrc[pos] = src;
}

// ---------------- layer 1: gather per dst (warp/dst) + bias + BN + ReLU ----------------
__global__ void gat1_gather_kernel(const float* __restrict__ b1,
                                   const float* __restrict__ gamma,
                                   const float* __restrict__ beta,
                                   const float* __restrict__ mean,
                                   const float* __restrict__ var, int n) {
    int w = (blockIdx.x * blockDim.x + threadIdx.x) >> 5;
    int lane = threadIdx.x & 31;
    if (w >= n) return;
    int h = lane >> 3;
    int beg = g_row[w], end = g_row[w + 1];
    float ad = g_ad1[w * 4 + h];

    float m = __int_as_float(0xff800000);
    for (int e = beg + (lane & 7); e < end; e += 8) {
        int s = g_csrc[e];
        m = fmaxf(m, lrelu(g_as1[s * 4 + h] + ad));
    }
    m = fmaxf(m, __shfl_xor_sync(0xffffffffu, m, 1));
    m = fmaxf(m, __shfl_xor_sync(0xffffffffu, m, 2));
    m = fmaxf(m, __shfl_xor_sync(0xffffffffu, m, 4));

    float4 acc = make_float4(0.f, 0.f, 0.f, 0.f);
    float ssum = 0.f;
    for (int e0 = beg; e0 < end; e0 += 32) {
        int e = e0 + lane;
        int sl = (e < end) ? g_csrc[e] : 0;
        int cnt = min(32, end - e0);
        for (int j = 0; j < cnt; j++) {
            int sj = __shfl_sync(0xffffffffu, sl, j);
            float p = __expf(lrelu(g_as1[sj * 4 + h] + ad) - m);
            ssum += p;
            float4 hv = *(const float4*)&g_h1[sj * 128 + lane * 4];
            acc.x += p * hv.x;
            acc.y += p * hv.y;
            acc.z += p * hv.z;
            acc.w += p * hv.w;
        }
    }

    int ch = lane * 4;
    float inv = 1.f / ssum;
    float4 o;
    float* op = &g_acc[w * 128 + ch];
#pragma unroll
    for (int j = 0; j < 4; j++) {
        float v = ((&acc.x)[j]) * inv + b1[ch + j];
        v = gamma[ch + j] * (v - mean[ch + j]) * rsqrtf(var[ch + j] + EPS_BN) + beta[ch + j];
        (&o.x)[j] = fmaxf(v, 0.f);
    }
    *(float4*)op = o;
}

// ---------------- layer 2: gather per dst (warp/dst) + bias + BN ----------------
__global__ void gat2_gather_kernel(float* __restrict__ out,
                                   const float* __restrict__ b2,
                                   const float* __restrict__ gamma,
                                   const float* __restrict__ beta,
                                   const float* __restrict__ mean,
                                   const float* __restrict__ var, int n) {
    int w = (blockIdx.x * blockDim.x + threadIdx.x) >> 5;
    int lane = threadIdx.x & 31;
    if (w >= n) return;
    int beg = g_row[w], end = g_row[w + 1];
    float ad = g_ad2[w];

    float m = __int_as_float(0xff800000);
    for (int e = beg + lane; e < end; e += 32) {
        int s = g_csrc[e];
        m = fmaxf(m, lrelu(g_as2[s] + ad));
    }
#pragma unroll
    for (int off = 16; off > 0; off >>= 1)
        m = fmaxf(m, __shfl_xor_sync(0xffffffffu, m, off));

    float2 acc = make_float2(0.f, 0.f);
    float ssum = 0.f;
    for (int e0 = beg; e0 < end; e0 += 32) {
        int e = e0 + lane;
        int sl = (e < end) ? g_csrc[e] : 0;
        int cnt = min(32, end - e0);
        for (int j = 0; j < cnt; j++) {
            int sj = __shfl_sync(0xffffffffu, sl, j);
            float p = __expf(lrelu(g_as2[sj] + ad) - m);
            ssum += p;
            float2 hv = *(const float2*)&g_h1[sj * 64 + lane * 2];
            acc.x += p * hv.x;
            acc.y += p * hv.y;
        }
    }

    int ch = lane * 2;
    float inv = 1.f / ssum;
    float vx = acc.x * inv + b2[ch];
    float vy = acc.y * inv + b2[ch + 1];
    vx = gamma[ch] * (vx - mean[ch]) * rsqrtf(var[ch] + EPS_BN) + beta[ch];
    vy = gamma[ch + 1] * (vy - mean[ch + 1]) * rsqrtf(var[ch + 1] + EPS_BN) + beta[ch + 1];
    *(float2*)&out[w * 64 + ch] = make_float2(vx, vy);
}

// ---------------- launcher ----------------
extern "C" void kernel_launch(void* const* d_in, const int* in_sizes, int n_in,
                              void* d_out, int out_size) {
    const float* x        = (const float*)d_in[0];
    const int*   ei       = (const int*)d_in[1];   // int32 (JAX demotes int64)
    const float* W1       = (const float*)d_in[2];
    const float* att_src1 = (const float*)d_in[3];
    const float* att_dst1 = (const float*)d_in[4];
    const float* b1       = (const float*)d_in[5];
    const float* bn1_g    = (const float*)d_in[6];
    const float* bn1_b    = (const float*)d_in[7];
    const float* bn1_m    = (const float*)d_in[8];
    const float* bn1_v    = (const float*)d_in[9];
    const float* W2       = (const float*)d_in[10];
    const float* att_src2 = (const float*)d_in[11];
    const float* att_dst2 = (const float*)d_in[12];
    const float* b2       = (const float*)d_in[13];
    const float* bn2_g    = (const float*)d_in[14];
    const float* bn2_b    = (const float*)d_in[15];
    const float* bn2_m    = (const float*)d_in[16];
    const float* bn2_v    = (const float*)d_in[17];
    float* out = (float*)d_out;

    int n = in_sizes[0] / 128;
    int E = in_sizes[1] / 2;
    int ET = E + n;
    int nb = (n + SCAN_CHUNK - 1) / SCAN_CHUNK;

    float* h1;
    float* acc;
    cudaGetSymbolAddress((void**)&h1, g_h1);
    cudaGetSymbolAddress((void**)&acc, g_acc);

    const int B = 256;

    // ---- layer 1 GEMM + fused scores (also zeroes CSR counters) ----
    gemm_fused_kernel<128, 128, 1><<<(n + 127) / 128, 256>>>(x, W1, h1, att_src1, att_dst1, n);

    // ---- CSR build (dst-sorted src lists, includes self-loops) ----
    hist_kernel<<<(ET + B - 1) / B, B>>>(ei, E, n);
    scan_part_kernel<<<nb, 256>>>(n);
    scan_top_kernel<<<1, SCAN_BLOCKS>>>(nb, n);
    scan_down_kernel<<<nb, 256>>>(n);
    scatter_kernel<<<(ET + B - 1) / B, B>>>(ei, E, n);

    // ---- layer 1 gather (softmax + aggregate + bias + BN + ReLU) ----
    gat1_gather_kernel<<<(n * 32 + B - 1) / B, B>>>(b1, bn1_g, bn1_b, bn1_m, bn1_v, n);

    // ---- layer 2 GEMM + fused scores ----
    gemm_fused_kernel<256, 64, 2><<<(n + 255) / 256, 256>>>(acc, W2, h1, att_src2, att_dst2, n);

    // ---- layer 2 gather ----
    gat2_gather_kernel<<<(n * 32 + B - 1) / B, B>>>(out, b2, bn2_g, bn2_b, bn2_m, bn2_v, n);
}

// round 6
// speedup vs baseline: 2.9059x; 1.0074x over previous
#include <cuda_runtime.h>
#include <cuda_fp16.h>

#define NMAX 100000
#define EMAX 1600000
#define ETMAX (EMAX + NMAX)
#define SCAN_CHUNK 1024
#define SCAN_BLOCKS ((NMAX + SCAN_CHUNK - 1) / SCAN_CHUNK)

// ---------------- scratch (static device globals; no allocation) ----------------
__device__ __align__(16) float g_h1[NMAX * 128];    // layer2 GEMM out (fp32)
__device__ __align__(16) __half g_h1h[NMAX * 128];  // layer1 GEMM out (fp16, gather operand)
__device__ __align__(16) float g_acc[NMAX * 128];   // layer1 output (post BN/ReLU)
__device__ __align__(16) float g_as1[NMAX * 4];
__device__ __align__(16) float g_ad1[NMAX * 4];
__device__ __align__(16) float g_as2[NMAX];
__device__ __align__(16) float g_ad2[NMAX];
__device__ int g_cnt[NMAX];
__device__ int g_row[NMAX + 1];
__device__ int g_cur[NMAX];
__device__ int g_csrc[ETMAX];
__device__ int g_part[SCAN_BLOCKS + 1];

#define NEG_SLOPE 0.2f
#define EPS_BN 1e-5f

__device__ __forceinline__ float lrelu(float v) {
    return v > 0.f ? v : NEG_SLOPE * v;
}

// ---------------- fused GEMM + attention scores ----------------
// C[n,BN] = A[n,128] @ W[128,BN]; 8x8 register tile per thread, BK=16.
// FUSE==1: write h as fp16 to g_h1h, write g_as1/g_ad1 (4 heads), zero g_cnt.
// FUSE==2: write fp32 C, write g_as2/g_ad2 (1 head).
template <int BM, int BN, int FUSE>
__global__ void __launch_bounds__(256) gemm_fused_kernel(
    const float* __restrict__ A, const float* __restrict__ W,
    float* __restrict__ C,
    const float* __restrict__ att_s, const float* __restrict__ att_d, int n) {
    constexpr int BK = 16;
    constexpr int TX = BN / 8;            // 16 (BN=128) or 8 (BN=64)
    constexpr int NT = (BM / 8) * TX;     // 256 both configs

    __shared__ __align__(16) float xs[BK][BM + 4];  // transposed A tile (+4 pad)
    __shared__ __align__(16) float ws[BK][BN];

    int tid = threadIdx.x;
    int tx = tid % TX;
    int ty = tid / TX;
    int row0 = blockIdx.x * BM;

    float acc[8][8];
#pragma unroll
    for (int i = 0; i < 8; i++)
#pragma unroll
        for (int j = 0; j < 8; j++) acc[i][j] = 0.f;

    for (int k0 = 0; k0 < 128; k0 += BK) {
        __syncthreads();
        // load A tile (BM x 16) -> xs transposed
#pragma unroll
        for (int rep = 0; rep < BM / 64; rep++) {
            int i = tid + rep * NT;       // float4 index in [0, BM*4)
            int r = i >> 2, c4 = i & 3;
            int gr = row0 + r;
            float4 v = make_float4(0.f, 0.f, 0.f, 0.f);
            if (gr < n) v = *(const float4*)&A[gr * 128 + k0 + c4 * 4];
            xs[c4 * 4 + 0][r] = v.x;
            xs[c4 * 4 + 1][r] = v.y;
            xs[c4 * 4 + 2][r] = v.z;
            xs[c4 * 4 + 3][r] = v.w;
        }
        // load W tile (16 x BN), fully coalesced
#pragma unroll
        for (int rep = 0; rep < (BK * BN / 4) / NT; rep++) {
            int i = tid + rep * NT;
            int kr = i / (BN / 4), c4 = i % (BN / 4);
            *(float4*)&ws[kr][c4 * 4] = *(const float4*)&W[(k0 + kr) * BN + c4 * 4];
        }
        __syncthreads();
#pragma unroll
        for (int kk = 0; kk < BK; kk++) {
            float a[8], b[8];
            *(float4*)&a[0] = *(const float4*)&xs[kk][ty * 8];
            *(float4*)&a[4] = *(const float4*)&xs[kk][ty * 8 + 4];
            *(float4*)&b[0] = *(const float4*)&ws[kk][tx * 8];
            *(float4*)&b[4] = *(const float4*)&ws[kk][tx * 8 + 4];
#pragma unroll
            for (int i = 0; i < 8; i++)
#pragma unroll
                for (int j = 0; j < 8; j++) acc[i][j] += a[i] * b[j];
        }
    }

    // store h
    if (FUSE == 1) {
        // fp16 store (gather operand); fp32 h1 never needed for layer 1
#pragma unroll
        for (int i = 0; i < 8; i++) {
            int gr = row0 + ty * 8 + i;
            if (gr < n) {
                __half2 p0 = __float22half2_rn(make_float2(acc[i][0], acc[i][1]));
                __half2 p1 = __float22half2_rn(make_float2(acc[i][2], acc[i][3]));
                __half2 p2 = __float22half2_rn(make_float2(acc[i][4], acc[i][5]));
                __half2 p3 = __float22half2_rn(make_float2(acc[i][6], acc[i][7]));
                uint4 pk;
                pk.x = *(unsigned*)&p0;
                pk.y = *(unsigned*)&p1;
                pk.z = *(unsigned*)&p2;
                pk.w = *(unsigned*)&p3;
                *(uint4*)&g_h1h[gr * 128 + tx * 8] = pk;
            }
        }
    } else {
#pragma unroll
        for (int i = 0; i < 8; i++) {
            int gr = row0 + ty * 8 + i;
            if (gr < n) {
                *(float4*)&C[gr * BN + tx * 8] =
                    make_float4(acc[i][0], acc[i][1], acc[i][2], acc[i][3]);
                *(float4*)&C[gr * BN + tx * 8 + 4] =
                    make_float4(acc[i][4], acc[i][5], acc[i][6], acc[i][7]);
            }
        }
    }

    // fused attention scores
    float as_r[8], ad_r[8];
#pragma unroll
    for (int j = 0; j < 8; j++) {
        as_r[j] = att_s[tx * 8 + j];
        ad_r[j] = att_d[tx * 8 + j];
    }
    float sa[8], sd[8];
#pragma unroll
    for (int i = 0; i < 8; i++) {
        float s = 0.f, d = 0.f;
#pragma unroll
        for (int j = 0; j < 8; j++) {
            s += acc[i][j] * as_r[j];
            d += acc[i][j] * ad_r[j];
        }
        sa[i] = s;
        sd[i] = d;
    }
    if (FUSE == 1) {
        // head = tx/4; reduce over 4 consecutive lanes (tx%4 group)
#pragma unroll
        for (int i = 0; i < 8; i++) {
            sa[i] += __shfl_xor_sync(0xffffffffu, sa[i], 1);
            sa[i] += __shfl_xor_sync(0xffffffffu, sa[i], 2);
            sd[i] += __shfl_xor_sync(0xffffffffu, sd[i], 1);
            sd[i] += __shfl_xor_sync(0xffffffffu, sd[i], 2);
        }
        if ((tx & 3) == 0) {
            int h = tx >> 2;
#pragma unroll
            for (int i = 0; i < 8; i++) {
                int gr = row0 + ty * 8 + i;
                if (gr < n) {
                    g_as1[gr * 4 + h] = sa[i];
                    g_ad1[gr * 4 + h] = sd[i];
                }
            }
        }
        // zero CSR counters for this block's rows
        if (tid < BM) {
            int gr = row0 + tid;
            if (gr < n) g_cnt[gr] = 0;
        }
    } else {
        // single head: reduce over all 8 tx lanes
#pragma unroll
        for (int i = 0; i < 8; i++) {
            sa[i] += __shfl_xor_sync(0xffffffffu, sa[i], 1);
            sa[i] += __shfl_xor_sync(0xffffffffu, sa[i], 2);
            sa[i] += __shfl_xor_sync(0xffffffffu, sa[i], 4);
            sd[i] += __shfl_xor_sync(0xffffffffu, sd[i], 1);
            sd[i] += __shfl_xor_sync(0xffffffffu, sd[i], 2);
            sd[i] += __shfl_xor_sync(0xffffffffu, sd[i], 4);
        }
        if (tx == 0) {
#pragma unroll
            for (int i = 0; i < 8; i++) {
                int gr = row0 + ty * 8 + i;
                if (gr < n) {
                    g_as2[gr] = sa[i];
                    g_ad2[gr] = sd[i];
                }
            }
        }
    }
}

// ---------------- CSR build: histogram over dst ----------------
__global__ void hist_kernel(const int* __restrict__ ei, int E, int n) {
    int e = blockIdx.x * blockDim.x + threadIdx.x;
    int ET = E + n;
    if (e >= ET) return;
    int dst = (e < E) ? ei[E + e] : (e - E);
    atomicAdd(&g_cnt[dst], 1);
}

// ---------------- CSR build: two-level parallel exclusive scan ----------------
__global__ void scan_part_kernel(int n) {
    __shared__ int sh[256];
    int blk = blockIdx.x;
    int t = threadIdx.x;
    int base = blk * SCAN_CHUNK + t * 4;
    int s = 0;
#pragma unroll
    for (int i = 0; i < 4; i++) {
        int idx = base + i;
        if (idx < n) s += g_cnt[idx];
    }
    sh[t] = s;
    __syncthreads();
#pragma unroll
    for (int off = 128; off > 0; off >>= 1) {
        if (t < off) sh[t] += sh[t + off];
        __syncthreads();
    }
    if (t == 0) g_part[blk] = sh[0];
}

__global__ void scan_top_kernel(int nb, int n) {
    __shared__ int sh[SCAN_BLOCKS];
    int t = threadIdx.x;
    int v = (t < nb) ? g_part[t] : 0;
    sh[t] = v;
    __syncthreads();
    for (int off = 1; off < SCAN_BLOCKS; off <<= 1) {
        int u = (t >= off) ? sh[t - off] : 0;
        __syncthreads();
        sh[t] += u;
        __syncthreads();
    }
    if (t < nb) g_part[t] = sh[t] - v;  // exclusive
    if (t == nb - 1) g_row[n] = sh[t];  // total
}

__global__ void scan_down_kernel(int n) {
    __shared__ int sh[256];
    int blk = blockIdx.x;
    int t = threadIdx.x;
    int base = blk * SCAN_CHUNK + t * 4;
    int v[4];
    int s = 0;
#pragma unroll
    for (int i = 0; i < 4; i++) {
        int idx = base + i;
        v[i] = (idx < n) ? g_cnt[idx] : 0;
        s += v[i];
    }
    sh[t] = s;
    __syncthreads();
    for (int off = 1; off < 256; off <<= 1) {
        int u = (t >= off) ? sh[t - off] : 0;
        __syncthreads();
        sh[t] += u;
        __syncthreads();
    }
    int running = sh[t] - s + g_part[blk];
#pragma unroll
    for (int i = 0; i < 4; i++) {
        int idx = base + i;
        if (idx < n) {
            g_row[idx] = running;
            g_cur[idx] = running;
            running += v[i];
        }
    }
}

// ---------------- CSR build: scatter src by dst ----------------
__global__ void scatter_kernel(const int* __restrict__ ei, int E, int n) {
    int e = blockIdx.x * blockDim.x + threadIdx.x;
    int ET = E + n;
    if (e >= ET) return;
    int src, dst;
    if (e < E) { src = ei[e]; dst = ei[E + e]; }
    else       { src = e - E; dst = src; }
    int pos = atomicAdd(&g_cur[dst], 1);
    g_csrc[pos] = src;
}

// ---------------- layer 1: gather per dst (warp/dst) + bias + BN + ReLU ----------------
__global__ void gat1_gather_kernel(const float* __restrict__ b1,
                                   const float* __restrict__ gamma,
                                   const float* __restrict__ beta,
                                   const float* __restrict__ mean,
                                   const float* __restrict__ var, int n) {
    int w = (blockIdx.x * blockDim.x + threadIdx.x) >> 5;
    int lane = threadIdx.x & 31;
    if (w >= n) return;
    int h = lane >> 3;
    int beg = g_row[w], end = g_row[w + 1];
    float ad = g_ad1[w * 4 + h];

    float m = __int_as_float(0xff800000);
    for (int e = beg + (lane & 7); e < end; e += 8) {
        int s = g_csrc[e];
        m = fmaxf(m, lrelu(g_as1[s * 4 + h] + ad));
    }
    m = fmaxf(m, __shfl_xor_sync(0xffffffffu, m, 1));
    m = fmaxf(m, __shfl_xor_sync(0xffffffffu, m, 2));
    m = fmaxf(m, __shfl_xor_sync(0xffffffffu, m, 4));

    float4 acc = make_float4(0.f, 0.f, 0.f, 0.f);
    float ssum = 0.f;
    for (int e0 = beg; e0 < end; e0 += 32) {
        int e = e0 + lane;
        int sl = (e < end) ? g_csrc[e] : 0;
        int cnt = min(32, end - e0);
        for (int j = 0; j < cnt; j++) {
            int sj = __shfl_sync(0xffffffffu, sl, j);
            float p = __expf(lrelu(g_as1[sj * 4 + h] + ad) - m);
            ssum += p;
            uint2 hv2 = *(const uint2*)&g_h1h[sj * 128 + lane * 4];
            float2 f01 = __half22float2(*(__half2*)&hv2.x);
            float2 f23 = __half22float2(*(__half2*)&hv2.y);
            acc.x += p * f01.x;
            acc.y += p * f01.y;
            acc.z += p * f23.x;
            acc.w += p * f23.y;
        }
    }

    int ch = lane * 4;
    float inv = 1.f / ssum;
    float4 o;
    float* op = &g_acc[w * 128 + ch];
#pragma unroll
    for (int j = 0; j < 4; j++) {
        float v = ((&acc.x)[j]) * inv + b1[ch + j];
        v = gamma[ch + j] * (v - mean[ch + j]) * rsqrtf(var[ch + j] + EPS_BN) + beta[ch + j];
        (&o.x)[j] = fmaxf(v, 0.f);
    }
    *(float4*)op = o;
}

// ---------------- layer 2: gather per dst (warp/dst) + bias + BN ----------------
__global__ void gat2_gather_kernel(float* __restrict__ out,
                                   const float* __restrict__ b2,
                                   const float* __restrict__ gamma,
                                   const float* __restrict__ beta,
                                   const float* __restrict__ mean,
                                   const float* __restrict__ var, int n) {
    int w = (blockIdx.x * blockDim.x + threadIdx.x) >> 5;
    int lane = threadIdx.x & 31;
    if (w >= n) return;
    int beg = g_row[w], end = g_row[w + 1];
    float ad = g_ad2[w];

    float m = __int_as_float(0xff800000);
    for (int e = beg + lane; e < end; e += 32) {
        int s = g_csrc[e];
        m = fmaxf(m, lrelu(g_as2[s] + ad));
    }
#pragma unroll
    for (int off = 16; off > 0; off >>= 1)
        m = fmaxf(m, __shfl_xor_sync(0xffffffffu, m, off));

    float2 acc = make_float2(0.f, 0.f);
    float ssum = 0.f;
    for (int e0 = beg; e0 < end; e0 += 32) {
        int e = e0 + lane;
        int sl = (e < end) ? g_csrc[e] : 0;
        int cnt = min(32, end - e0);
        for (int j = 0; j < cnt; j++) {
            int sj = __shfl_sync(0xffffffffu, sl, j);
            float p = __expf(lrelu(g_as2[sj] + ad) - m);
            ssum += p;
            float2 hv = *(const float2*)&g_h1[sj * 64 + lane * 2];
            acc.x += p * hv.x;
            acc.y += p * hv.y;
        }
    }

    int ch = lane * 2;
    float inv = 1.f / ssum;
    float vx = acc.x * inv + b2[ch];
    float vy = acc.y * inv + b2[ch + 1];
    vx = gamma[ch] * (vx - mean[ch]) * rsqrtf(var[ch] + EPS_BN) + beta[ch];
    vy = gamma[ch + 1] * (vy - mean[ch + 1]) * rsqrtf(var[ch + 1] + EPS_BN) + beta[ch + 1];
    *(float2*)&out[w * 64 + ch] = make_float2(vx, vy);
}

// ---------------- launcher ----------------
extern "C" void kernel_launch(void* const* d_in, const int* in_sizes, int n_in,
                              void* d_out, int out_size) {
    const float* x        = (const float*)d_in[0];
    const int*   ei       = (const int*)d_in[1];   // int32 (JAX demotes int64)
    const float* W1       = (const float*)d_in[2];
    const float* att_src1 = (const float*)d_in[3];
    const float* att_dst1 = (const float*)d_in[4];
    const float* b1       = (const float*)d_in[5];
    const float* bn1_g    = (const float*)d_in[6];
    const float* bn1_b    = (const float*)d_in[7];
    const float* bn1_m    = (const float*)d_in[8];
    const float* bn1_v    = (const float*)d_in[9];
    const float* W2       = (const float*)d_in[10];
    const float* att_src2 = (const float*)d_in[11];
    const float* att_dst2 = (const float*)d_in[12];
    const float* b2       = (const float*)d_in[13];
    const float* bn2_g    = (const float*)d_in[14];
    const float* bn2_b    = (const float*)d_in[15];
    const float* bn2_m    = (const float*)d_in[16];
    const float* bn2_v    = (const float*)d_in[17];
    float* out = (float*)d_out;

    int n = in_sizes[0] / 128;
    int E = in_sizes[1] / 2;
    int ET = E + n;
    int nb = (n + SCAN_CHUNK - 1) / SCAN_CHUNK;

    float* h1;
    float* acc;
    cudaGetSymbolAddress((void**)&h1, g_h1);
    cudaGetSymbolAddress((void**)&acc, g_acc);

    const int B = 256;

    // ---- layer 1 GEMM + fused scores (h -> fp16; also zeroes CSR counters) ----
    gemm_fused_kernel<128, 128, 1><<<(n + 127) / 128, 256>>>(x, W1, h1, att_src1, att_dst1, n);

    // ---- CSR build (dst-sorted src lists, includes self-loops) ----
    hist_kernel<<<(ET + B - 1) / B, B>>>(ei, E, n);
    scan_part_kernel<<<nb, 256>>>(n);
    scan_top_kernel<<<1, SCAN_BLOCKS>>>(nb, n);
    scan_down_kernel<<<nb, 256>>>(n);
    scatter_kernel<<<(ET + B - 1) / B, B>>>(ei, E, n);

    // ---- layer 1 gather (softmax + aggregate + bias + BN + ReLU) ----
    gat1_gather_kernel<<<(n * 32 + B - 1) / B, B>>>(b1, bn1_g, bn1_b, bn1_m, bn1_v, n);

    // ---- layer 2 GEMM + fused scores ----
    gemm_fused_kernel<256, 64, 2><<<(n + 255) / 256, 256>>>(acc, W2, h1, att_src2, att_dst2, n);

    // ---- layer 2 gather ----
    gat2_gather_kernel<<<(n * 32 + B - 1) / B, B>>>(out, b2, bn2_g, bn2_b, bn2_m, bn2_v, n);
}

// round 7
// speedup vs baseline: 3.8262x; 1.3167x over previous
#include <cuda_runtime.h>
#include <cuda_fp16.h>

#define NMAX 100000
#define EMAX 1600000
#define ETMAX (EMAX + NMAX)
#define SCAN_CHUNK 1024
#define SCAN_BLOCKS ((NMAX + SCAN_CHUNK - 1) / SCAN_CHUNK)

// ---------------- scratch (static device globals; no allocation) ----------------
__device__ __align__(16) float g_h1[NMAX * 128];    // layer2 GEMM out (fp32)
__device__ __align__(16) __half g_h1h[NMAX * 128];  // layer1 GEMM out (fp16, gather operand)
__device__ __align__(16) float g_acc[NMAX * 128];   // layer1 output (post BN/ReLU)
__device__ __align__(16) float g_as1[NMAX * 4];
__device__ __align__(16) float g_ad1[NMAX * 4];
__device__ __align__(16) float g_as2[NMAX];
__device__ __align__(16) float g_ad2[NMAX];
__device__ int g_cnt[NMAX];
__device__ int g_row[NMAX + 1];
__device__ int g_cur[NMAX];
__device__ int g_csrc[ETMAX];
__device__ int g_part[SCAN_BLOCKS + 1];

#define NEG_SLOPE 0.2f
#define EPS_BN 1e-5f

__device__ __forceinline__ float lrelu(float v) {
    return v > 0.f ? v : NEG_SLOPE * v;
}

__device__ __forceinline__ float f2tf32(float f) {
    unsigned u;
    asm("cvt.rna.tf32.f32 %0, %1;" : "=r"(u) : "f"(f));
    return __uint_as_float(u);
}

__device__ __forceinline__ void mma_tf32(float* c, const unsigned* a, const unsigned* b) {
    asm volatile(
        "mma.sync.aligned.m16n8k8.row.col.f32.tf32.tf32.f32 "
        "{%0,%1,%2,%3}, {%4,%5,%6,%7}, {%8,%9}, {%0,%1,%2,%3};\n"
        : "+f"(c[0]), "+f"(c[1]), "+f"(c[2]), "+f"(c[3])
        : "r"(a[0]), "r"(a[1]), "r"(a[2]), "r"(a[3]), "r"(b[0]), "r"(b[1]));
}

// ---------------- layer 1 GEMM (tensor core, tf32) + fused scores ----------------
// h1h[n,128] = fp16(x @ W1); scores g_as1/g_ad1; zero g_cnt.
// Block 128x128, 8 warps (2M x 4N), warp tile 64x32, BK=32.
__global__ void __launch_bounds__(256) gemm1_tc_kernel(
    const float* __restrict__ A, const float* __restrict__ W,
    const float* __restrict__ att_s, const float* __restrict__ att_d, int n) {
    __shared__ float sA[128][36];   // [m][k], pitch 36 -> frag LDS conflict-free
    __shared__ float sW[32][136];   // [k][n], pitch 136 -> frag LDS conflict-free

    int tid = threadIdx.x;
    int warp = tid >> 5, lane = tid & 31;
    int gid = lane >> 2, tig = lane & 3;
    int mwarp = warp >> 2, nwarp = warp & 3;
    int row0 = blockIdx.x * 128;

    float acc[4][4][4];
#pragma unroll
    for (int mt = 0; mt < 4; mt++)
#pragma unroll
        for (int nt = 0; nt < 4; nt++)
#pragma unroll
            for (int r = 0; r < 4; r++) acc[mt][nt][r] = 0.f;

    for (int kc = 0; kc < 4; kc++) {
        int k0 = kc * 32;
        __syncthreads();
        // A chunk: 128x32, 4 float4 per thread
#pragma unroll
        for (int rep = 0; rep < 4; rep++) {
            int f = tid + rep * 256;
            int r = f >> 3, c4 = f & 7;
            int gr = row0 + r;
            float4 v = make_float4(0.f, 0.f, 0.f, 0.f);
            if (gr < n) v = *(const float4*)&A[gr * 128 + k0 + c4 * 4];
            float4 t = make_float4(f2tf32(v.x), f2tf32(v.y), f2tf32(v.z), f2tf32(v.w));
            *(float4*)&sA[r][c4 * 4] = t;
        }
        // W chunk: 32x128, 4 float4 per thread
#pragma unroll
        for (int rep = 0; rep < 4; rep++) {
            int f = tid + rep * 256;
            int kr = f >> 5, c4 = f & 31;
            float4 v = *(const float4*)&W[(k0 + kr) * 128 + c4 * 4];
            float4 t = make_float4(f2tf32(v.x), f2tf32(v.y), f2tf32(v.z), f2tf32(v.w));
            *(float4*)&sW[kr][c4 * 4] = t;
        }
        __syncthreads();
#pragma unroll
        for (int ks = 0; ks < 4; ks++) {
            int kk = ks * 8;
            unsigned b[4][2], a[4][4];
#pragma unroll
            for (int nt = 0; nt < 4; nt++) {
                int c = nwarp * 32 + nt * 8 + gid;
                b[nt][0] = __float_as_uint(sW[kk + tig][c]);
                b[nt][1] = __float_as_uint(sW[kk + tig + 4][c]);
            }
#pragma unroll
            for (int mt = 0; mt < 4; mt++) {
                int r = mwarp * 64 + mt * 16 + gid;
                a[mt][0] = __float_as_uint(sA[r][kk + tig]);
                a[mt][1] = __float_as_uint(sA[r + 8][kk + tig]);
                a[mt][2] = __float_as_uint(sA[r][kk + tig + 4]);
                a[mt][3] = __float_as_uint(sA[r + 8][kk + tig + 4]);
            }
#pragma unroll
            for (int mt = 0; mt < 4; mt++)
#pragma unroll
                for (int nt = 0; nt < 4; nt++) mma_tf32(acc[mt][nt], a[mt], b[nt]);
        }
    }

    // epilogue: fp16 h store + fused per-head scores (head == nwarp)
    float asr[8], adr[8];
#pragma unroll
    for (int nt = 0; nt < 4; nt++) {
        int c = nwarp * 32 + nt * 8 + tig * 2;
        asr[nt * 2 + 0] = att_s[c];
        asr[nt * 2 + 1] = att_s[c + 1];
        adr[nt * 2 + 0] = att_d[c];
        adr[nt * 2 + 1] = att_d[c + 1];
    }
#pragma unroll
    for (int mt = 0; mt < 4; mt++) {
#pragma unroll
        for (int half = 0; half < 2; half++) {
            int r = row0 + mwarp * 64 + mt * 16 + gid + half * 8;
            float sa = 0.f, sd = 0.f;
            if (r < n) {
#pragma unroll
                for (int nt = 0; nt < 4; nt++) {
                    float c0 = acc[mt][nt][half * 2 + 0];
                    float c1 = acc[mt][nt][half * 2 + 1];
                    int col = nwarp * 32 + nt * 8 + tig * 2;
                    *(__half2*)&g_h1h[r * 128 + col] =
                        __float22half2_rn(make_float2(c0, c1));
                    sa += c0 * asr[nt * 2] + c1 * asr[nt * 2 + 1];
                    sd += c0 * adr[nt * 2] + c1 * adr[nt * 2 + 1];
                }
            }
            sa += __shfl_xor_sync(0xffffffffu, sa, 1);
            sa += __shfl_xor_sync(0xffffffffu, sa, 2);
            sd += __shfl_xor_sync(0xffffffffu, sd, 1);
            sd += __shfl_xor_sync(0xffffffffu, sd, 2);
            if (tig == 0 && r < n) {
                g_as1[r * 4 + nwarp] = sa;
                g_ad1[r * 4 + nwarp] = sd;
            }
        }
    }
    if (tid < 128) {
        int gr = row0 + tid;
        if (gr < n) g_cnt[gr] = 0;
    }
}

// ---------------- layer 2 GEMM (tensor core, tf32) + fused scores ----------------
// h1[n,64] = g_acc @ W2 (fp32); scores g_as2/g_ad2.
// Block 128x64, 8 warps all in M, warp tile 16x64, BK=32.
__global__ void __launch_bounds__(256) gemm2_tc_kernel(
    const float* __restrict__ W,
    const float* __restrict__ att_s, const float* __restrict__ att_d, int n) {
    __shared__ float sA[128][36];
    __shared__ float sW[32][72];

    int tid = threadIdx.x;
    int warp = tid >> 5, lane = tid & 31;
    int gid = lane >> 2, tig = lane & 3;
    int row0 = blockIdx.x * 128;

    float acc[8][4];
#pragma unroll
    for (int nt = 0; nt < 8; nt++)
#pragma unroll
        for (int r = 0; r < 4; r++) acc[nt][r] = 0.f;

    for (int kc = 0; kc < 4; kc++) {
        int k0 = kc * 32;
        __syncthreads();
#pragma unroll
        for (int rep = 0; rep < 4; rep++) {
            int f = tid + rep * 256;
            int r = f >> 3, c4 = f & 7;
            int gr = row0 + r;
            float4 v = make_float4(0.f, 0.f, 0.f, 0.f);
            if (gr < n) v = *(const float4*)&g_acc[gr * 128 + k0 + c4 * 4];
            float4 t = make_float4(f2tf32(v.x), f2tf32(v.y), f2tf32(v.z), f2tf32(v.w));
            *(float4*)&sA[r][c4 * 4] = t;
        }
        // W chunk: 32x64 = 512 float4, 2 per thread
#pragma unroll
        for (int rep = 0; rep < 2; rep++) {
            int f = tid + rep * 256;
            int kr = f >> 4, c4 = f & 15;
            float4 v = *(const float4*)&W[(k0 + kr) * 64 + c4 * 4];
            float4 t = make_float4(f2tf32(v.x), f2tf32(v.y), f2tf32(v.z), f2tf32(v.w));
            *(float4*)&sW[kr][c4 * 4] = t;
        }
        __syncthreads();
#pragma unroll
        for (int ks = 0; ks < 4; ks++) {
            int kk = ks * 8;
            unsigned a[4], b[8][2];
            {
                int r = warp * 16 + gid;
                a[0] = __float_as_uint(sA[r][kk + tig]);
                a[1] = __float_as_uint(sA[r + 8][kk + tig]);
                a[2] = __float_as_uint(sA[r][kk + tig + 4]);
                a[3] = __float_as_uint(sA[r + 8][kk + tig + 4]);
            }
#pragma unroll
            for (int nt = 0; nt < 8; nt++) {
                int c = nt * 8 + gid;
                b[nt][0] = __float_as_uint(sW[kk + tig][c]);
                b[nt][1] = __float_as_uint(sW[kk + tig + 4][c]);
            }
#pragma unroll
            for (int nt = 0; nt < 8; nt++) mma_tf32(acc[nt], a, b[nt]);
        }
    }

    // epilogue: fp32 h store + fused scores (single head)
    float asr[16], adr[16];
#pragma unroll
    for (int nt = 0; nt < 8; nt++) {
        int c = nt * 8 + tig * 2;
        asr[nt * 2 + 0] = att_s[c];
        asr[nt * 2 + 1] = att_s[c + 1];
        adr[nt * 2 + 0] = att_d[c];
        adr[nt * 2 + 1] = att_d[c + 1];
    }
#pragma unroll
    for (int half = 0; half < 2; half++) {
        int r = row0 + warp * 16 + gid + half * 8;
        float sa = 0.f, sd = 0.f;
        if (r < n) {
#pragma unroll
            for (int nt = 0; nt < 8; nt++) {
                float c0 = acc[nt][half * 2 + 0];
                float c1 = acc[nt][half * 2 + 1];
                int col = nt * 8 + tig * 2;
                *(float2*)&g_h1[r * 64 + col] = make_float2(c0, c1);
                sa += c0 * asr[nt * 2] + c1 * asr[nt * 2 + 1];
                sd += c0 * adr[nt * 2] + c1 * adr[nt * 2 + 1];
            }
        }
        sa += __shfl_xor_sync(0xffffffffu, sa, 1);
        sa += __shfl_xor_sync(0xffffffffu, sa, 2);
        sd += __shfl_xor_sync(0xffffffffu, sd, 1);
        sd += __shfl_xor_sync(0xffffffffu, sd, 2);
        if (tig == 0 && r < n) {
            g_as2[r] = sa;
            g_ad2[r] = sd;
        }
    }
}

// ---------------- CSR build: histogram over dst ----------------
__global__ void hist_kernel(const int* __restrict__ ei, int E, int n) {
    int e = blockIdx.x * blockDim.x + threadIdx.x;
    int ET = E + n;
    if (e >= ET) return;
    int dst = (e < E) ? ei[E + e] : (e - E);
    atomicAdd(&g_cnt[dst], 1);
}

// ---------------- CSR build: two-level parallel exclusive scan ----------------
__global__ void scan_part_kernel(int n) {
    __shared__ int sh[256];
    int blk = blockIdx.x;
    int t = threadIdx.x;
    int base = blk * SCAN_CHUNK + t * 4;
    int s = 0;
#pragma unroll
    for (int i = 0; i < 4; i++) {
        int idx = base + i;
        if (idx < n) s += g_cnt[idx];
    }
    sh[t] = s;
    __syncthreads();
#pragma unroll
    for (int off = 128; off > 0; off >>= 1) {
        if (t < off) sh[t] += sh[t + off];
        __syncthreads();
    }
    if (t == 0) g_part[blk] = sh[0];
}

__global__ void scan_top_kernel(int nb, int n) {
    __shared__ int sh[SCAN_BLOCKS];
    int t = threadIdx.x;
    int v = (t < nb) ? g_part[t] : 0;
    sh[t] = v;
    __syncthreads();
    for (int off = 1; off < SCAN_BLOCKS; off <<= 1) {
        int u = (t >= off) ? sh[t - off] : 0;
        __syncthreads();
        sh[t] += u;
        __syncthreads();
    }
    if (t < nb) g_part[t] = sh[t] - v;  // exclusive
    if (t == nb - 1) g_row[n] = sh[t];  // total
}

__global__ void scan_down_kernel(int n) {
    __shared__ int sh[256];
    int blk = blockIdx.x;
    int t = threadIdx.x;
    int base = blk * SCAN_CHUNK + t * 4;
    int v[4];
    int s = 0;
#pragma unroll
    for (int i = 0; i < 4; i++) {
        int idx = base + i;
        v[i] = (idx < n) ? g_cnt[idx] : 0;
        s += v[i];
    }
    sh[t] = s;
    __syncthreads();
    for (int off = 1; off < 256; off <<= 1) {
        int u = (t >= off) ? sh[t - off] : 0;
        __syncthreads();
        sh[t] += u;
        __syncthreads();
    }
    int running = sh[t] - s + g_part[blk];
#pragma unroll
    for (int i = 0; i < 4; i++) {
        int idx = base + i;
        if (idx < n) {
            g_row[idx] = running;
            g_cur[idx] = running;
            running += v[i];
        }
    }
}

// ---------------- CSR build: scatter src by dst ----------------
__global__ void scatter_kernel(const int* __restrict__ ei, int E, int n) {
    int e = blockIdx.x * blockDim.x + threadIdx.x;
    int ET = E + n;
    if (e >= ET) return;
    int src, dst;
    if (e < E) { src = ei[e]; dst = ei[E + e]; }
    else       { src = e - E; dst = src; }
    int pos = atomicAdd(&g_cur[dst], 1);
    g_csrc[pos] = src;
}

// ---------------- layer 1: gather per dst (warp/dst) + bias + BN + ReLU ----------------
__global__ void gat1_gather_kernel(const float* __restrict__ b1,
                                   const float* __restrict__ gamma,
                                   const float* __restrict__ beta,
                                   const float* __restrict__ mean,
                                   const float* __restrict__ var, int n) {
    int w = (blockIdx.x * blockDim.x + threadIdx.x) >> 5;
    int lane = threadIdx.x & 31;
    if (w >= n) return;
    int h = lane >> 3;
    int beg = g_row[w], end = g_row[w + 1];
    float ad = g_ad1[w * 4 + h];

    float m = __int_as_float(0xff800000);
    for (int e = beg + (lane & 7); e < end; e += 8) {
        int s = g_csrc[e];
        m = fmaxf(m, lrelu(g_as1[s * 4 + h] + ad));
    }
    m = fmaxf(m, __shfl_xor_sync(0xffffffffu, m, 1));
    m = fmaxf(m, __shfl_xor_sync(0xffffffffu, m, 2));
    m = fmaxf(m, __shfl_xor_sync(0xffffffffu, m, 4));

    float4 acc = make_float4(0.f, 0.f, 0.f, 0.f);
    float ssum = 0.f;
    for (int e0 = beg; e0 < end; e0 += 32) {
        int e = e0 + lane;
        int sl = (e < end) ? g_csrc[e] : 0;
        int cnt = min(32, end - e0);
        for (int j = 0; j < cnt; j++) {
            int sj = __shfl_sync(0xffffffffu, sl, j);
            float p = __expf(lrelu(g_as1[sj * 4 + h] + ad) - m);
            ssum += p;
            uint2 hv2 = *(const uint2*)&g_h1h[sj * 128 + lane * 4];
            float2 f01 = __half22float2(*(__half2*)&hv2.x);
            float2 f23 = __half22float2(*(__half2*)&hv2.y);
            acc.x += p * f01.x;
            acc.y += p * f01.y;
            acc.z += p * f23.x;
            acc.w += p * f23.y;
        }
    }

    int ch = lane * 4;
    float inv = 1.f / ssum;
    float4 o;
    float* op = &g_acc[w * 128 + ch];
#pragma unroll
    for (int j = 0; j < 4; j++) {
        float v = ((&acc.x)[j]) * inv + b1[ch + j];
        v = gamma[ch + j] * (v - mean[ch + j]) * rsqrtf(var[ch + j] + EPS_BN) + beta[ch + j];
        (&o.x)[j] = fmaxf(v, 0.f);
    }
    *(float4*)op = o;
}

// ---------------- layer 2: gather per dst (warp/dst) + bias + BN ----------------
__global__ void gat2_gather_kernel(float* __restrict__ out,
                                   const float* __restrict__ b2,
                                   const float* __restrict__ gamma,
                                   const float* __restrict__ beta,
                                   const float* __restrict__ mean,
                                   const float* __restrict__ var, int n) {
    int w = (blockIdx.x * blockDim.x + threadIdx.x) >> 5;
    int lane = threadIdx.x & 31;
    if (w >= n) return;
    int beg = g_row[w], end = g_row[w + 1];
    float ad = g_ad2[w];

    float m = __int_as_float(0xff800000);
    for (int e = beg + lane; e < end; e += 32) {
        int s = g_csrc[e];
        m = fmaxf(m, lrelu(g_as2[s] + ad));
    }
#pragma unroll
    for (int off = 16; off > 0; off >>= 1)
        m = fmaxf(m, __shfl_xor_sync(0xffffffffu, m, off));

    float2 acc = make_float2(0.f, 0.f);
    float ssum = 0.f;
    for (int e0 = beg; e0 < end; e0 += 32) {
        int e = e0 + lane;
        int sl = (e < end) ? g_csrc[e] : 0;
        int cnt = min(32, end - e0);
        for (int j = 0; j < cnt; j++) {
            int sj = __shfl_sync(0xffffffffu, sl, j);
            float p = __expf(lrelu(g_as2[sj] + ad) - m);
            ssum += p;
            float2 hv = *(const float2*)&g_h1[sj * 64 + lane * 2];
            acc.x += p * hv.x;
            acc.y += p * hv.y;
        }
    }

    int ch = lane * 2;
    float inv = 1.f / ssum;
    float vx = acc.x * inv + b2[ch];
    float vy = acc.y * inv + b2[ch + 1];
    vx = gamma[ch] * (vx - mean[ch]) * rsqrtf(var[ch] + EPS_BN) + beta[ch];
    vy = gamma[ch + 1] * (vy - mean[ch + 1]) * rsqrtf(var[ch + 1] + EPS_BN) + beta[ch + 1];
    *(float2*)&out[w * 64 + ch] = make_float2(vx, vy);
}

// ---------------- launcher ----------------
extern "C" void kernel_launch(void* const* d_in, const int* in_sizes, int n_in,
                              void* d_out, int out_size) {
    const float* x        = (const float*)d_in[0];
    const int*   ei       = (const int*)d_in[1];   // int32 (JAX demotes int64)
    const float* W1       = (const float*)d_in[2];
    const float* att_src1 = (const float*)d_in[3];
    const float* att_dst1 = (const float*)d_in[4];
    const float* b1       = (const float*)d_in[5];
    const float* bn1_g    = (const float*)d_in[6];
    const float* bn1_b    = (const float*)d_in[7];
    const float* bn1_m    = (const float*)d_in[8];
    const float* bn1_v    = (const float*)d_in[9];
    const float* W2       = (const float*)d_in[10];
    const float* att_src2 = (const float*)d_in[11];
    const float* att_dst2 = (const float*)d_in[12];
    const float* b2       = (const float*)d_in[13];
    const float* bn2_g    = (const float*)d_in[14];
    const float* bn2_b    = (const float*)d_in[15];
    const float* bn2_m    = (const float*)d_in[16];
    const float* bn2_v    = (const float*)d_in[17];
    float* out = (float*)d_out;

    int n = in_sizes[0] / 128;
    int E = in_sizes[1] / 2;
    int ET = E + n;
    int nb = (n + SCAN_CHUNK - 1) / SCAN_CHUNK;

    const int B = 256;

    // ---- layer 1 GEMM (tensor core) + fused scores (h -> fp16; zeroes g_cnt) ----
    gemm1_tc_kernel<<<(n + 127) / 128, 256>>>(x, W1, att_src1, att_dst1, n);

    // ---- CSR build (dst-sorted src lists, includes self-loops) ----
    hist_kernel<<<(ET + B - 1) / B, B>>>(ei, E, n);
    scan_part_kernel<<<nb, 256>>>(n);
    scan_top_kernel<<<1, SCAN_BLOCKS>>>(nb, n);
    scan_down_kernel<<<nb, 256>>>(n);
    scatter_kernel<<<(ET + B - 1) / B, B>>>(ei, E, n);

    // ---- layer 1 gather (softmax + aggregate + bias + BN + ReLU) ----
    gat1_gather_kernel<<<(n * 32 + B - 1) / B, B>>>(b1, bn1_g, bn1_b, bn1_m, bn1_v, n);

    // ---- layer 2 GEMM (tensor core) + fused scores ----
    gemm2_tc_kernel<<<(n + 127) / 128, 256>>>(W2, att_src2, att_dst2, n);

    // ---- layer 2 gather ----
    gat2_gather_kernel<<<(n * 32 + B - 1) / B, B>>>(out, b2, bn2_g, bn2_b, bn2_m, bn2_v, n);
}

// round 8
// speedup vs baseline: 4.2729x; 1.1167x over previous
#include <cuda_runtime.h>
#include <cuda_fp16.h>

#define NMAX 100000
#define EMAX 1600000
#define ETMAX (EMAX + NMAX)
#define SCAN_CHUNK 1024
#define SCAN_BLOCKS ((NMAX + SCAN_CHUNK - 1) / SCAN_CHUNK)

// ---------------- scratch (static device globals; no allocation) ----------------
__device__ __align__(16) float g_h1[NMAX * 128];    // layer2 GEMM out (fp32)
__device__ __align__(16) __half g_h1h[NMAX * 128];  // layer1 GEMM out (fp16, gather operand)
__device__ __align__(16) float g_acc[NMAX * 128];   // layer1 output (post BN/ReLU)
__device__ __align__(16) float g_as1[NMAX * 4];
__device__ __align__(16) float g_ad1[NMAX * 4];
__device__ __align__(16) float g_as2[NMAX];
__device__ __align__(16) float g_ad2[NMAX];
__device__ float g_gmax[8];    // [0..3]=max as1 per head, [4..7]=max ad1 per head
__device__ float g_gmax2[2];   // [0]=max as2, [1]=max ad2
__device__ int g_cnt[NMAX];
__device__ int g_row[NMAX + 1];
__device__ int g_cur[NMAX];
__device__ int g_csrc[ETMAX];
__device__ int g_part[SCAN_BLOCKS + 1];

#define NEG_SLOPE 0.2f
#define EPS_BN 1e-5f

__device__ __forceinline__ float lrelu(float v) {
    return v > 0.f ? v : NEG_SLOPE * v;
}

// float atomic max via sign-split trick (valid for all non-NaN floats)
__device__ __forceinline__ void atomicMaxF(float* addr, float v) {
    if (v >= 0.f) atomicMax((int*)addr, __float_as_int(v));
    else          atomicMin((unsigned int*)addr, __float_as_uint(v));
}

__device__ __forceinline__ float f2tf32(float f) {
    unsigned u;
    asm("cvt.rna.tf32.f32 %0, %1;" : "=r"(u) : "f"(f));
    return __uint_as_float(u);
}

__device__ __forceinline__ void mma_tf32(float* c, const unsigned* a, const unsigned* b) {
    asm volatile(
        "mma.sync.aligned.m16n8k8.row.col.f32.tf32.tf32.f32 "
        "{%0,%1,%2,%3}, {%4,%5,%6,%7}, {%8,%9}, {%0,%1,%2,%3};\n"
        : "+f"(c[0]), "+f"(c[1]), "+f"(c[2]), "+f"(c[3])
        : "r"(a[0]), "r"(a[1]), "r"(a[2]), "r"(a[3]), "r"(b[0]), "r"(b[1]));
}

// ---------------- init global maxes ----------------
__global__ void init_gmax_kernel() {
    int t = threadIdx.x;
    if (t < 8) g_gmax[t] = __int_as_float(0xff800000);
    if (t < 2) g_gmax2[t] = __int_as_float(0xff800000);
}

// ---------------- layer 1 GEMM (tensor core, tf32) + fused scores ----------------
__global__ void __launch_bounds__(256) gemm1_tc_kernel(
    const float* __restrict__ A, const float* __restrict__ W,
    const float* __restrict__ att_s, const float* __restrict__ att_d, int n) {
    __shared__ float sA[128][36];
    __shared__ float sW[32][136];

    int tid = threadIdx.x;
    int warp = tid >> 5, lane = tid & 31;
    int gid = lane >> 2, tig = lane & 3;
    int mwarp = warp >> 2, nwarp = warp & 3;
    int row0 = blockIdx.x * 128;

    float acc[4][4][4];
#pragma unroll
    for (int mt = 0; mt < 4; mt++)
#pragma unroll
        for (int nt = 0; nt < 4; nt++)
#pragma unroll
            for (int r = 0; r < 4; r++) acc[mt][nt][r] = 0.f;

    for (int kc = 0; kc < 4; kc++) {
        int k0 = kc * 32;
        __syncthreads();
#pragma unroll
        for (int rep = 0; rep < 4; rep++) {
            int f = tid + rep * 256;
            int r = f >> 3, c4 = f & 7;
            int gr = row0 + r;
            float4 v = make_float4(0.f, 0.f, 0.f, 0.f);
            if (gr < n) v = *(const float4*)&A[gr * 128 + k0 + c4 * 4];
            float4 t = make_float4(f2tf32(v.x), f2tf32(v.y), f2tf32(v.z), f2tf32(v.w));
            *(float4*)&sA[r][c4 * 4] = t;
        }
#pragma unroll
        for (int rep = 0; rep < 4; rep++) {
            int f = tid + rep * 256;
            int kr = f >> 5, c4 = f & 31;
            float4 v = *(const float4*)&W[(k0 + kr) * 128 + c4 * 4];
            float4 t = make_float4(f2tf32(v.x), f2tf32(v.y), f2tf32(v.z), f2tf32(v.w));
            *(float4*)&sW[kr][c4 * 4] = t;
        }
        __syncthreads();
#pragma unroll
        for (int ks = 0; ks < 4; ks++) {
            int kk = ks * 8;
            unsigned b[4][2], a[4][4];
#pragma unroll
            for (int nt = 0; nt < 4; nt++) {
                int c = nwarp * 32 + nt * 8 + gid;
                b[nt][0] = __float_as_uint(sW[kk + tig][c]);
                b[nt][1] = __float_as_uint(sW[kk + tig + 4][c]);
            }
#pragma unroll
            for (int mt = 0; mt < 4; mt++) {
                int r = mwarp * 64 + mt * 16 + gid;
                a[mt][0] = __float_as_uint(sA[r][kk + tig]);
                a[mt][1] = __float_as_uint(sA[r + 8][kk + tig]);
                a[mt][2] = __float_as_uint(sA[r][kk + tig + 4]);
                a[mt][3] = __float_as_uint(sA[r + 8][kk + tig + 4]);
            }
#pragma unroll
            for (int mt = 0; mt < 4; mt++)
#pragma unroll
                for (int nt = 0; nt < 4; nt++) mma_tf32(acc[mt][nt], a[mt], b[nt]);
        }
    }

    // epilogue: fp16 h store + fused per-head scores (head == nwarp)
    float asr[8], adr[8];
#pragma unroll
    for (int nt = 0; nt < 4; nt++) {
        int c = nwarp * 32 + nt * 8 + tig * 2;
        asr[nt * 2 + 0] = att_s[c];
        asr[nt * 2 + 1] = att_s[c + 1];
        adr[nt * 2 + 0] = att_d[c];
        adr[nt * 2 + 1] = att_d[c + 1];
    }
    float mxs = __int_as_float(0xff800000), mxd = __int_as_float(0xff800000);
#pragma unroll
    for (int mt = 0; mt < 4; mt++) {
#pragma unroll
        for (int half = 0; half < 2; half++) {
            int r = row0 + mwarp * 64 + mt * 16 + gid + half * 8;
            float sa = 0.f, sd = 0.f;
            if (r < n) {
#pragma unroll
                for (int nt = 0; nt < 4; nt++) {
                    float c0 = acc[mt][nt][half * 2 + 0];
                    float c1 = acc[mt][nt][half * 2 + 1];
                    int col = nwarp * 32 + nt * 8 + tig * 2;
                    *(__half2*)&g_h1h[r * 128 + col] =
                        __float22half2_rn(make_float2(c0, c1));
                    sa += c0 * asr[nt * 2] + c1 * asr[nt * 2 + 1];
                    sd += c0 * adr[nt * 2] + c1 * adr[nt * 2 + 1];
                }
            }
            sa += __shfl_xor_sync(0xffffffffu, sa, 1);
            sa += __shfl_xor_sync(0xffffffffu, sa, 2);
            sd += __shfl_xor_sync(0xffffffffu, sd, 1);
            sd += __shfl_xor_sync(0xffffffffu, sd, 2);
            if (r < n) {
                mxs = fmaxf(mxs, sa);
                mxd = fmaxf(mxd, sd);
                if (tig == 0) {
                    g_as1[r * 4 + nwarp] = sa;
                    g_ad1[r * 4 + nwarp] = sd;
                }
            }
        }
    }
    // warp-reduced global max per head
#pragma unroll
    for (int off = 16; off > 0; off >>= 1) {
        mxs = fmaxf(mxs, __shfl_xor_sync(0xffffffffu, mxs, off));
        mxd = fmaxf(mxd, __shfl_xor_sync(0xffffffffu, mxd, off));
    }
    if (lane == 0) {
        atomicMaxF(&g_gmax[nwarp], mxs);
        atomicMaxF(&g_gmax[4 + nwarp], mxd);
    }
    if (tid < 128) {
        int gr = row0 + tid;
        if (gr < n) g_cnt[gr] = 0;
    }
}

// ---------------- layer 2 GEMM (tensor core, tf32) + fused scores ----------------
__global__ void __launch_bounds__(256) gemm2_tc_kernel(
    const float* __restrict__ W,
    const float* __restrict__ att_s, const float* __restrict__ att_d, int n) {
    __shared__ float sA[128][36];
    __shared__ float sW[32][72];

    int tid = threadIdx.x;
    int warp = tid >> 5, lane = tid & 31;
    int gid = lane >> 2, tig = lane & 3;
    int row0 = blockIdx.x * 128;

    float acc[8][4];
#pragma unroll
    for (int nt = 0; nt < 8; nt++)
#pragma unroll
        for (int r = 0; r < 4; r++) acc[nt][r] = 0.f;

    for (int kc = 0; kc < 4; kc++) {
        int k0 = kc * 32;
        __syncthreads();
#pragma unroll
        for (int rep = 0; rep < 4; rep++) {
            int f = tid + rep * 256;
            int r = f >> 3, c4 = f & 7;
            int gr = row0 + r;
            float4 v = make_float4(0.f, 0.f, 0.f, 0.f);
            if (gr < n) v = *(const float4*)&g_acc[gr * 128 + k0 + c4 * 4];
            float4 t = make_float4(f2tf32(v.x), f2tf32(v.y), f2tf32(v.z), f2tf32(v.w));
            *(float4*)&sA[r][c4 * 4] = t;
        }
#pragma unroll
        for (int rep = 0; rep < 2; rep++) {
            int f = tid + rep * 256;
            int kr = f >> 4, c4 = f & 15;
            float4 v = *(const float4*)&W[(k0 + kr) * 64 + c4 * 4];
            float4 t = make_float4(f2tf32(v.x), f2tf32(v.y), f2tf32(v.z), f2tf32(v.w));
            *(float4*)&sW[kr][c4 * 4] = t;
        }
        __syncthreads();
#pragma unroll
        for (int ks = 0; ks < 4; ks++) {
            int kk = ks * 8;
            unsigned a[4], b[8][2];
            {
                int r = warp * 16 + gid;
                a[0] = __float_as_uint(sA[r][kk + tig]);
                a[1] = __float_as_uint(sA[r + 8][kk + tig]);
                a[2] = __float_as_uint(sA[r][kk + tig + 4]);
                a[3] = __float_as_uint(sA[r + 8][kk + tig + 4]);
            }
#pragma unroll
            for (int nt = 0; nt < 8; nt++) {
                int c = nt * 8 + gid;
                b[nt][0] = __float_as_uint(sW[kk + tig][c]);
                b[nt][1] = __float_as_uint(sW[kk + tig + 4][c]);
            }
#pragma unroll
            for (int nt = 0; nt < 8; nt++) mma_tf32(acc[nt], a, b[nt]);
        }
    }

    // epilogue: fp32 h store + fused scores (single head)
    float asr[16], adr[16];
#pragma unroll
    for (int nt = 0; nt < 8; nt++) {
        int c = nt * 8 + tig * 2;
        asr[nt * 2 + 0] = att_s[c];
        asr[nt * 2 + 1] = att_s[c + 1];
        adr[nt * 2 + 0] = att_d[c];
        adr[nt * 2 + 1] = att_d[c + 1];
    }
    float mxs = __int_as_float(0xff800000), mxd = __int_as_float(0xff800000);
#pragma unroll
    for (int half = 0; half < 2; half++) {
        int r = row0 + warp * 16 + gid + half * 8;
        float sa = 0.f, sd = 0.f;
        if (r < n) {
#pragma unroll
            for (int nt = 0; nt < 8; nt++) {
                float c0 = acc[nt][half * 2 + 0];
                float c1 = acc[nt][half * 2 + 1];
                int col = nt * 8 + tig * 2;
                *(float2*)&g_h1[r * 64 + col] = make_float2(c0, c1);
                sa += c0 * asr[nt * 2] + c1 * asr[nt * 2 + 1];
                sd += c0 * adr[nt * 2] + c1 * adr[nt * 2 + 1];
            }
        }
        sa += __shfl_xor_sync(0xffffffffu, sa, 1);
        sa += __shfl_xor_sync(0xffffffffu, sa, 2);
        sd += __shfl_xor_sync(0xffffffffu, sd, 1);
        sd += __shfl_xor_sync(0xffffffffu, sd, 2);
        if (r < n) {
            mxs = fmaxf(mxs, sa);
            mxd = fmaxf(mxd, sd);
            if (tig == 0) {
                g_as2[r] = sa;
                g_ad2[r] = sd;
            }
        }
    }
#pragma unroll
    for (int off = 16; off > 0; off >>= 1) {
        mxs = fmaxf(mxs, __shfl_xor_sync(0xffffffffu, mxs, off));
        mxd = fmaxf(mxd, __shfl_xor_sync(0xffffffffu, mxd, off));
    }
    if (lane == 0) {
        atomicMaxF(&g_gmax2[0], mxs);
        atomicMaxF(&g_gmax2[1], mxd);
    }
}

// ---------------- CSR build ----------------
__global__ void hist_kernel(const int* __restrict__ ei, int E, int n) {
    int e = blockIdx.x * blockDim.x + threadIdx.x;
    int ET = E + n;
    if (e >= ET) return;
    int dst = (e < E) ? ei[E + e] : (e - E);
    atomicAdd(&g_cnt[dst], 1);
}

__global__ void scan_part_kernel(int n) {
    __shared__ int sh[256];
    int blk = blockIdx.x;
    int t = threadIdx.x;
    int base = blk * SCAN_CHUNK + t * 4;
    int s = 0;
#pragma unroll
    for (int i = 0; i < 4; i++) {
        int idx = base + i;
        if (idx < n) s += g_cnt[idx];
    }
    sh[t] = s;
    __syncthreads();
#pragma unroll
    for (int off = 128; off > 0; off >>= 1) {
        if (t < off) sh[t] += sh[t + off];
        __syncthreads();
    }
    if (t == 0) g_part[blk] = sh[0];
}

__global__ void scan_top_kernel(int nb, int n) {
    __shared__ int sh[SCAN_BLOCKS];
    int t = threadIdx.x;
    int v = (t < nb) ? g_part[t] : 0;
    sh[t] = v;
    __syncthreads();
    for (int off = 1; off < SCAN_BLOCKS; off <<= 1) {
        int u = (t >= off) ? sh[t - off] : 0;
        __syncthreads();
        sh[t] += u;
        __syncthreads();
    }
    if (t < nb) g_part[t] = sh[t] - v;
    if (t == nb - 1) g_row[n] = sh[t];
}

__global__ void scan_down_kernel(int n) {
    __shared__ int sh[256];
    int blk = blockIdx.x;
    int t = threadIdx.x;
    int base = blk * SCAN_CHUNK + t * 4;
    int v[4];
    int s = 0;
#pragma unroll
    for (int i = 0; i < 4; i++) {
        int idx = base + i;
        v[i] = (idx < n) ? g_cnt[idx] : 0;
        s += v[i];
    }
    sh[t] = s;
    __syncthreads();
    for (int off = 1; off < 256; off <<= 1) {
        int u = (t >= off) ? sh[t - off] : 0;
        __syncthreads();
        sh[t] += u;
        __syncthreads();
    }
    int running = sh[t] - s + g_part[blk];
#pragma unroll
    for (int i = 0; i < 4; i++) {
        int idx = base + i;
        if (idx < n) {
            g_row[idx] = running;
            g_cur[idx] = running;
            running += v[i];
        }
    }
}

__global__ void scatter_kernel(const int* __restrict__ ei, int E, int n) {
    int e = blockIdx.x * blockDim.x + threadIdx.x;
    int ET = E + n;
    if (e >= ET) return;
    int src, dst;
    if (e < E) { src = ei[e]; dst = ei[E + e]; }
    else       { src = e - E; dst = src; }
    int pos = atomicAdd(&g_cur[dst], 1);
    g_csrc[pos] = src;
}

// ---------------- layer 1: single-pass gather (warp/dst), global ub softmax ----------------
__global__ void gat1_gather_kernel(const float* __restrict__ b1,
                                   const float* __restrict__ gamma,
                                   const float* __restrict__ beta,
                                   const float* __restrict__ mean,
                                   const float* __restrict__ var, int n) {
    int w = (blockIdx.x * blockDim.x + threadIdx.x) >> 5;
    int lane = threadIdx.x & 31;
    if (w >= n) return;
    int h = lane >> 3;
    int beg = g_row[w], end = g_row[w + 1];
    float ad = g_ad1[w * 4 + h];
    float ub = lrelu(g_gmax[h] + g_gmax[4 + h]);

    float4 acc = make_float4(0.f, 0.f, 0.f, 0.f);
    float ssum = 0.f;
    int cb = lane * 4;  // channel base
    int e = beg;
    for (; e + 4 <= end; e += 4) {
        int s0 = g_csrc[e + 0];
        int s1 = g_csrc[e + 1];
        int s2 = g_csrc[e + 2];
        int s3 = g_csrc[e + 3];
        float a0 = g_as1[s0 * 4 + h];
        float a1 = g_as1[s1 * 4 + h];
        float a2 = g_as1[s2 * 4 + h];
        float a3 = g_as1[s3 * 4 + h];
        uint2 v0 = *(const uint2*)&g_h1h[s0 * 128 + cb];
        uint2 v1 = *(const uint2*)&g_h1h[s1 * 128 + cb];
        uint2 v2 = *(const uint2*)&g_h1h[s2 * 128 + cb];
        uint2 v3 = *(const uint2*)&g_h1h[s3 * 128 + cb];
        float p0 = __expf(lrelu(a0 + ad) - ub);
        float p1 = __expf(lrelu(a1 + ad) - ub);
        float p2 = __expf(lrelu(a2 + ad) - ub);
        float p3 = __expf(lrelu(a3 + ad) - ub);
        ssum += (p0 + p1) + (p2 + p3);
        float2 f;
        f = __half22float2(*(__half2*)&v0.x); acc.x += p0 * f.x; acc.y += p0 * f.y;
        f = __half22float2(*(__half2*)&v0.y); acc.z += p0 * f.x; acc.w += p0 * f.y;
        f = __half22float2(*(__half2*)&v1.x); acc.x += p1 * f.x; acc.y += p1 * f.y;
        f = __half22float2(*(__half2*)&v1.y); acc.z += p1 * f.x; acc.w += p1 * f.y;
        f = __half22float2(*(__half2*)&v2.x); acc.x += p2 * f.x; acc.y += p2 * f.y;
        f = __half22float2(*(__half2*)&v2.y); acc.z += p2 * f.x; acc.w += p2 * f.y;
        f = __half22float2(*(__half2*)&v3.x); acc.x += p3 * f.x; acc.y += p3 * f.y;
        f = __half22float2(*(__half2*)&v3.y); acc.z += p3 * f.x; acc.w += p3 * f.y;
    }
    for (; e < end; e++) {
        int s0 = g_csrc[e];
        float a0 = g_as1[s0 * 4 + h];
        uint2 v0 = *(const uint2*)&g_h1h[s0 * 128 + cb];
        float p0 = __expf(lrelu(a0 + ad) - ub);
        ssum += p0;
        float2 f;
        f = __half22float2(*(__half2*)&v0.x); acc.x += p0 * f.x; acc.y += p0 * f.y;
        f = __half22float2(*(__half2*)&v0.y); acc.z += p0 * f.x; acc.w += p0 * f.y;
    }

    float inv = 1.f / ssum;
    float4 o;
#pragma unroll
    for (int j = 0; j < 4; j++) {
        float v = ((&acc.x)[j]) * inv + b1[cb + j];
        v = gamma[cb + j] * (v - mean[cb + j]) * rsqrtf(var[cb + j] + EPS_BN) + beta[cb + j];
        (&o.x)[j] = fmaxf(v, 0.f);
    }
    *(float4*)&g_acc[w * 128 + cb] = o;
}

// ---------------- layer 2: single-pass gather (warp/dst), global ub softmax ----------------
__global__ void gat2_gather_kernel(float* __restrict__ out,
                                   const float* __restrict__ b2,
                                   const float* __restrict__ gamma,
                                   const float* __restrict__ beta,
                                   const float* __restrict__ mean,
                                   const float* __restrict__ var, int n) {
    int w = (blockIdx.x * blockDim.x + threadIdx.x) >> 5;
    int lane = threadIdx.x & 31;
    if (w >= n) return;
    int beg = g_row[w], end = g_row[w + 1];
    float ad = g_ad2[w];
    float ub = lrelu(g_gmax2[0] + g_gmax2[1]);

    float2 acc = make_float2(0.f, 0.f);
    float ssum = 0.f;
    int cb = lane * 2;
    int e = beg;
    for (; e + 4 <= end; e += 4) {
        int s0 = g_csrc[e + 0];
        int s1 = g_csrc[e + 1];
        int s2 = g_csrc[e + 2];
        int s3 = g_csrc[e + 3];
        float a0 = g_as2[s0];
        float a1 = g_as2[s1];
        float a2 = g_as2[s2];
        float a3 = g_as2[s3];
        float2 v0 = *(const float2*)&g_h1[s0 * 64 + cb];
        float2 v1 = *(const float2*)&g_h1[s1 * 64 + cb];
        float2 v2 = *(const float2*)&g_h1[s2 * 64 + cb];
        float2 v3 = *(const float2*)&g_h1[s3 * 64 + cb];
        float p0 = __expf(lrelu(a0 + ad) - ub);
        float p1 = __expf(lrelu(a1 + ad) - ub);
        float p2 = __expf(lrelu(a2 + ad) - ub);
        float p3 = __expf(lrelu(a3 + ad) - ub);
        ssum += (p0 + p1) + (p2 + p3);
        acc.x += p0 * v0.x + p1 * v1.x + p2 * v2.x + p3 * v3.x;
        acc.y += p0 * v0.y + p1 * v1.y + p2 * v2.y + p3 * v3.y;
    }
    for (; e < end; e++) {
        int s0 = g_csrc[e];
        float a0 = g_as2[s0];
        float2 v0 = *(const float2*)&g_h1[s0 * 64 + cb];
        float p0 = __expf(lrelu(a0 + ad) - ub);
        ssum += p0;
        acc.x += p0 * v0.x;
        acc.y += p0 * v0.y;
    }

    float inv = 1.f / ssum;
    float vx = acc.x * inv + b2[cb];
    float vy = acc.y * inv + b2[cb + 1];
    vx = gamma[cb] * (vx - mean[cb]) * rsqrtf(var[cb] + EPS_BN) + beta[cb];
    vy = gamma[cb + 1] * (vy - mean[cb + 1]) * rsqrtf(var[cb + 1] + EPS_BN) + beta[cb + 1];
    *(float2*)&out[w * 64 + cb] = make_float2(vx, vy);
}

// ---------------- launcher ----------------
extern "C" void kernel_launch(void* const* d_in, const int* in_sizes, int n_in,
                              void* d_out, int out_size) {
    const float* x        = (const float*)d_in[0];
    const int*   ei       = (const int*)d_in[1];   // int32 (JAX demotes int64)
    const float* W1       = (const float*)d_in[2];
    const float* att_src1 = (const float*)d_in[3];
    const float* att_dst1 = (const float*)d_in[4];
    const float* b1       = (const float*)d_in[5];
    const float* bn1_g    = (const float*)d_in[6];
    const float* bn1_b    = (const float*)d_in[7];
    const float* bn1_m    = (const float*)d_in[8];
    const float* bn1_v    = (const float*)d_in[9];
    const float* W2       = (const float*)d_in[10];
    const float* att_src2 = (const float*)d_in[11];
    const float* att_dst2 = (const float*)d_in[12];
    const float* b2       = (const float*)d_in[13];
    const float* bn2_g    = (const float*)d_in[14];
    const float* bn2_b    = (const float*)d_in[15];
    const float* bn2_m    = (const float*)d_in[16];
    const float* bn2_v    = (const float*)d_in[17];
    float* out = (float*)d_out;

    int n = in_sizes[0] / 128;
    int E = in_sizes[1] / 2;
    int ET = E + n;
    int nb = (n + SCAN_CHUNK - 1) / SCAN_CHUNK;

    const int B = 256;

    init_gmax_kernel<<<1, 32>>>();

    // ---- layer 1 GEMM (tensor core) + fused scores + global max ----
    gemm1_tc_kernel<<<(n + 127) / 128, 256>>>(x, W1, att_src1, att_dst1, n);

    // ---- CSR build ----
    hist_kernel<<<(ET + B - 1) / B, B>>>(ei, E, n);
    scan_part_kernel<<<nb, 256>>>(n);
    scan_top_kernel<<<1, SCAN_BLOCKS>>>(nb, n);
    scan_down_kernel<<<nb, 256>>>(n);
    scatter_kernel<<<(ET + B - 1) / B, B>>>(ei, E, n);

    // ---- layer 1 gather (single pass) ----
    gat1_gather_kernel<<<(n * 32 + B - 1) / B, B>>>(b1, bn1_g, bn1_b, bn1_m, bn1_v, n);

    // ---- layer 2 GEMM (tensor core) + fused scores + global max ----
    gemm2_tc_kernel<<<(n + 127) / 128, 256>>>(W2, att_src2, att_dst2, n);

    // ---- layer 2 gather (single pass) ----
    gat2_gather_kernel<<<(n * 32 + B - 1) / B, B>>>(out, b2, bn2_g, bn2_b, bn2_m, bn2_v, n);
}

// round 9
// speedup vs baseline: 4.3465x; 1.0172x over previous
#include <cuda_runtime.h>
#include <cuda_fp16.h>

#define NMAX 100000
#define EMAX 1600000
#define ETMAX (EMAX + NMAX)
#define SCAN_CHUNK 1024
#define SCAN_BLOCKS ((NMAX + SCAN_CHUNK - 1) / SCAN_CHUNK)

// ---------------- scratch (static device globals; no allocation) ----------------
__device__ __align__(16) float g_h1[NMAX * 128];    // (unused fp32 scratch; kept for layout stability)
__device__ __align__(16) __half g_h1h[NMAX * 128];  // layer1 h fp16; later reused for layer2 h fp16 (stride 64)
__device__ __align__(16) float g_acc[NMAX * 128];   // layer1 output (post BN/ReLU)
__device__ __align__(16) float g_as1[NMAX * 4];
__device__ __align__(16) float g_ad1[NMAX * 4];
__device__ __align__(16) float g_as2[NMAX];
__device__ __align__(16) float g_ad2[NMAX];
__device__ float g_gmax[8];    // [0..3]=max as1 per head, [4..7]=max ad1 per head
__device__ float g_gmax2[2];   // [0]=max as2, [1]=max ad2
__device__ int g_cnt[NMAX];    // INVARIANT: zero on entry to kernel_launch (re-zeroed by scan_down)
__device__ int g_row[NMAX + 1];
__device__ int g_cur[NMAX];
__device__ int g_csrc[ETMAX];
__device__ int g_part[SCAN_BLOCKS + 1];

#define NEG_SLOPE 0.2f
#define EPS_BN 1e-5f

__device__ __forceinline__ float lrelu(float v) {
    return v > 0.f ? v : NEG_SLOPE * v;
}

__device__ __forceinline__ void atomicMaxF(float* addr, float v) {
    if (v >= 0.f) atomicMax((int*)addr, __float_as_int(v));
    else          atomicMin((unsigned int*)addr, __float_as_uint(v));
}

__device__ __forceinline__ float f2tf32(float f) {
    unsigned u;
    asm("cvt.rna.tf32.f32 %0, %1;" : "=r"(u) : "f"(f));
    return __uint_as_float(u);
}

__device__ __forceinline__ void mma_tf32(float* c, const unsigned* a, const unsigned* b) {
    asm volatile(
        "mma.sync.aligned.m16n8k8.row.col.f32.tf32.tf32.f32 "
        "{%0,%1,%2,%3}, {%4,%5,%6,%7}, {%8,%9}, {%0,%1,%2,%3};\n"
        : "+f"(c[0]), "+f"(c[1]), "+f"(c[2]), "+f"(c[3])
        : "r"(a[0]), "r"(a[1]), "r"(a[2]), "r"(a[3]), "r"(b[0]), "r"(b[1]));
}

// ---------------- [1] histogram over dst (+ gmax init; g_cnt pre-zeroed invariant) ----------------
__global__ void hist_kernel(const int* __restrict__ ei, int E, int n) {
    if (blockIdx.x == 0 && threadIdx.x < 10) {
        float ninf = __int_as_float(0xff800000);
        if (threadIdx.x < 8) g_gmax[threadIdx.x] = ninf;
        else                 g_gmax2[threadIdx.x - 8] = ninf;
    }
    int e = blockIdx.x * blockDim.x + threadIdx.x;
    int ET = E + n;
    if (e >= ET) return;
    int dst = (e < E) ? ei[E + e] : (e - E);
    atomicAdd(&g_cnt[dst], 1);
}

// ---------------- [2] per-block partial sums ----------------
__global__ void scan_part_kernel(int n) {
    __shared__ int sh[256];
    int blk = blockIdx.x;
    int t = threadIdx.x;
    int base = blk * SCAN_CHUNK + t * 4;
    int s = 0;
#pragma unroll
    for (int i = 0; i < 4; i++) {
        int idx = base + i;
        if (idx < n) s += g_cnt[idx];
    }
    sh[t] = s;
    __syncthreads();
#pragma unroll
    for (int off = 128; off > 0; off >>= 1) {
        if (t < off) sh[t] += sh[t + off];
        __syncthreads();
    }
    if (t == 0) g_part[blk] = sh[0];
}

// ---------------- [3] down-sweep: in-block top scan + local scan + re-zero g_cnt ----------------
__global__ void scan_down_kernel(int n, int nb) {
    __shared__ int sp[128];
    __shared__ int sh[256];
    int blk = blockIdx.x;
    int t = threadIdx.x;

    // redundant scan of the <=98 block partials (inclusive)
    if (t < 128) sp[t] = (t < nb) ? g_part[t] : 0;
    __syncthreads();
    for (int off = 1; off < 128; off <<= 1) {
        int u = 0;
        if (t < 128 && t >= off) u = sp[t - off];
        __syncthreads();
        if (t < 128) sp[t] += u;
        __syncthreads();
    }
    if (blk == 0 && t == 0) g_row[n] = sp[nb - 1];
    int blockoff = sp[blk] - g_part[blk];  // exclusive offset of this block

    int base = blk * SCAN_CHUNK + t * 4;
    int v[4];
    int s = 0;
#pragma unroll
    for (int i = 0; i < 4; i++) {
        int idx = base + i;
        v[i] = (idx < n) ? g_cnt[idx] : 0;
        s += v[i];
    }
    sh[t] = s;
    __syncthreads();
    for (int off = 1; off < 256; off <<= 1) {
        int u = (t >= off) ? sh[t - off] : 0;
        __syncthreads();
        sh[t] += u;
        __syncthreads();
    }
    int running = sh[t] - s + blockoff;
#pragma unroll
    for (int i = 0; i < 4; i++) {
        int idx = base + i;
        if (idx < n) {
            g_row[idx] = running;
            g_cur[idx] = running;
            g_cnt[idx] = 0;  // restore zero invariant for next replay
            running += v[i];
        }
    }
}

// ---------------- [4] scatter src by dst ----------------
__global__ void scatter_kernel(const int* __restrict__ ei, int E, int n) {
    int e = blockIdx.x * blockDim.x + threadIdx.x;
    int ET = E + n;
    if (e >= ET) return;
    int src, dst;
    if (e < E) { src = ei[e]; dst = ei[E + e]; }
    else       { src = e - E; dst = src; }
    int pos = atomicAdd(&g_cur[dst], 1);
    g_csrc[pos] = src;
}

// ---------------- [5] layer 1 GEMM (tensor core, tf32) + fused scores + gmax ----------------
__global__ void __launch_bounds__(256) gemm1_tc_kernel(
    const float* __restrict__ A, const float* __restrict__ W,
    const float* __restrict__ att_s, const float* __restrict__ att_d, int n) {
    __shared__ float sA[128][36];
    __shared__ float sW[32][136];

    int tid = threadIdx.x;
    int warp = tid >> 5, lane = tid & 31;
    int gid = lane >> 2, tig = lane & 3;
    int mwarp = warp >> 2, nwarp = warp & 3;
    int row0 = blockIdx.x * 128;

    float acc[4][4][4];
#pragma unroll
    for (int mt = 0; mt < 4; mt++)
#pragma unroll
        for (int nt = 0; nt < 4; nt++)
#pragma unroll
            for (int r = 0; r < 4; r++) acc[mt][nt][r] = 0.f;

    for (int kc = 0; kc < 4; kc++) {
        int k0 = kc * 32;
        __syncthreads();
#pragma unroll
        for (int rep = 0; rep < 4; rep++) {
            int f = tid + rep * 256;
            int r = f >> 3, c4 = f & 7;
            int gr = row0 + r;
            float4 v = make_float4(0.f, 0.f, 0.f, 0.f);
            if (gr < n) v = *(const float4*)&A[gr * 128 + k0 + c4 * 4];
            float4 t = make_float4(f2tf32(v.x), f2tf32(v.y), f2tf32(v.z), f2tf32(v.w));
            *(float4*)&sA[r][c4 * 4] = t;
        }
#pragma unroll
        for (int rep = 0; rep < 4; rep++) {
            int f = tid + rep * 256;
            int kr = f >> 5, c4 = f & 31;
            float4 v = *(const float4*)&W[(k0 + kr) * 128 + c4 * 4];
            float4 t = make_float4(f2tf32(v.x), f2tf32(v.y), f2tf32(v.z), f2tf32(v.w));
            *(float4*)&sW[kr][c4 * 4] = t;
        }
        __syncthreads();
#pragma unroll
        for (int ks = 0; ks < 4; ks++) {
            int kk = ks * 8;
            unsigned b[4][2], a[4][4];
#pragma unroll
            for (int nt = 0; nt < 4; nt++) {
                int c = nwarp * 32 + nt * 8 + gid;
                b[nt][0] = __float_as_uint(sW[kk + tig][c]);
                b[nt][1] = __float_as_uint(sW[kk + tig + 4][c]);
            }
#pragma unroll
            for (int mt = 0; mt < 4; mt++) {
                int r = mwarp * 64 + mt * 16 + gid;
                a[mt][0] = __float_as_uint(sA[r][kk + tig]);
                a[mt][1] = __float_as_uint(sA[r + 8][kk + tig]);
                a[mt][2] = __float_as_uint(sA[r][kk + tig + 4]);
                a[mt][3] = __float_as_uint(sA[r + 8][kk + tig + 4]);
            }
#pragma unroll
            for (int mt = 0; mt < 4; mt++)
#pragma unroll
                for (int nt = 0; nt < 4; nt++) mma_tf32(acc[mt][nt], a[mt], b[nt]);
        }
    }

    float asr[8], adr[8];
#pragma unroll
    for (int nt = 0; nt < 4; nt++) {
        int c = nwarp * 32 + nt * 8 + tig * 2;
        asr[nt * 2 + 0] = att_s[c];
        asr[nt * 2 + 1] = att_s[c + 1];
        adr[nt * 2 + 0] = att_d[c];
        adr[nt * 2 + 1] = att_d[c + 1];
    }
    float mxs = __int_as_float(0xff800000), mxd = __int_as_float(0xff800000);
#pragma unroll
    for (int mt = 0; mt < 4; mt++) {
#pragma unroll
        for (int half = 0; half < 2; half++) {
            int r = row0 + mwarp * 64 + mt * 16 + gid + half * 8;
            float sa = 0.f, sd = 0.f;
            if (r < n) {
#pragma unroll
                for (int nt = 0; nt < 4; nt++) {
                    float c0 = acc[mt][nt][half * 2 + 0];
                    float c1 = acc[mt][nt][half * 2 + 1];
                    int col = nwarp * 32 + nt * 8 + tig * 2;
                    *(__half2*)&g_h1h[r * 128 + col] =
                        __float22half2_rn(make_float2(c0, c1));
                    sa += c0 * asr[nt * 2] + c1 * asr[nt * 2 + 1];
                    sd += c0 * adr[nt * 2] + c1 * adr[nt * 2 + 1];
                }
            }
            sa += __shfl_xor_sync(0xffffffffu, sa, 1);
            sa += __shfl_xor_sync(0xffffffffu, sa, 2);
            sd += __shfl_xor_sync(0xffffffffu, sd, 1);
            sd += __shfl_xor_sync(0xffffffffu, sd, 2);
            if (r < n) {
                mxs = fmaxf(mxs, sa);
                mxd = fmaxf(mxd, sd);
                if (tig == 0) {
                    g_as1[r * 4 + nwarp] = sa;
                    g_ad1[r * 4 + nwarp] = sd;
                }
            }
        }
    }
#pragma unroll
    for (int off = 16; off > 0; off >>= 1) {
        mxs = fmaxf(mxs, __shfl_xor_sync(0xffffffffu, mxs, off));
        mxd = fmaxf(mxd, __shfl_xor_sync(0xffffffffu, mxd, off));
    }
    if (lane == 0) {
        atomicMaxF(&g_gmax[nwarp], mxs);
        atomicMaxF(&g_gmax[4 + nwarp], mxd);
    }
}

// ---------------- [6] layer 1 gather (warp/dst), global-ub softmax, unroll 8/4/1 ----------------
__global__ void gat1_gather_kernel(const float* __restrict__ b1,
                                   const float* __restrict__ gamma,
                                   const float* __restrict__ beta,
                                   const float* __restrict__ mean,
                                   const float* __restrict__ var, int n) {
    int w = (blockIdx.x * blockDim.x + threadIdx.x) >> 5;
    int lane = threadIdx.x & 31;
    if (w >= n) return;
    int h = lane >> 3;
    int beg = g_row[w], end = g_row[w + 1];
    float ad = g_ad1[w * 4 + h];
    float ub = lrelu(g_gmax[h] + g_gmax[4 + h]);

    float4 acc = make_float4(0.f, 0.f, 0.f, 0.f);
    float ssum = 0.f;
    int cb = lane * 4;
    int e = beg;
    for (; e + 8 <= end; e += 8) {
        int sv[8];
#pragma unroll
        for (int j = 0; j < 8; j++) sv[j] = g_csrc[e + j];
        float av[8];
#pragma unroll
        for (int j = 0; j < 8; j++) av[j] = g_as1[sv[j] * 4 + h];
        uint2 hv[8];
#pragma unroll
        for (int j = 0; j < 8; j++) hv[j] = *(const uint2*)&g_h1h[sv[j] * 128 + cb];
#pragma unroll
        for (int j = 0; j < 8; j++) {
            float p = __expf(lrelu(av[j] + ad) - ub);
            ssum += p;
            float2 f01 = __half22float2(*(__half2*)&hv[j].x);
            float2 f23 = __half22float2(*(__half2*)&hv[j].y);
            acc.x += p * f01.x;
            acc.y += p * f01.y;
            acc.z += p * f23.x;
            acc.w += p * f23.y;
        }
    }
    for (; e + 4 <= end; e += 4) {
        int sv[4];
#pragma unroll
        for (int j = 0; j < 4; j++) sv[j] = g_csrc[e + j];
        float av[4];
#pragma unroll
        for (int j = 0; j < 4; j++) av[j] = g_as1[sv[j] * 4 + h];
        uint2 hv[4];
#pragma unroll
        for (int j = 0; j < 4; j++) hv[j] = *(const uint2*)&g_h1h[sv[j] * 128 + cb];
#pragma unroll
        for (int j = 0; j < 4; j++) {
            float p = __expf(lrelu(av[j] + ad) - ub);
            ssum += p;
            float2 f01 = __half22float2(*(__half2*)&hv[j].x);
            float2 f23 = __half22float2(*(__half2*)&hv[j].y);
            acc.x += p * f01.x;
            acc.y += p * f01.y;
            acc.z += p * f23.x;
            acc.w += p * f23.y;
        }
    }
    for (; e < end; e++) {
        int s0 = g_csrc[e];
        float a0 = g_as1[s0 * 4 + h];
        uint2 v0 = *(const uint2*)&g_h1h[s0 * 128 + cb];
        float p0 = __expf(lrelu(a0 + ad) - ub);
        ssum += p0;
        float2 f01 = __half22float2(*(__half2*)&v0.x);
        float2 f23 = __half22float2(*(__half2*)&v0.y);
        acc.x += p0 * f01.x;
        acc.y += p0 * f01.y;
        acc.z += p0 * f23.x;
        acc.w += p0 * f23.y;
    }

    float inv = 1.f / ssum;
    float4 o;
#pragma unroll
    for (int j = 0; j < 4; j++) {
        float v = ((&acc.x)[j]) * inv + b1[cb + j];
        v = gamma[cb + j] * (v - mean[cb + j]) * rsqrtf(var[cb + j] + EPS_BN) + beta[cb + j];
        (&o.x)[j] = fmaxf(v, 0.f);
    }
    *(float4*)&g_acc[w * 128 + cb] = o;
}

// ---------------- [7] layer 2 GEMM (tensor core, tf32): h2 -> fp16 (g_h1h), scores, gmax ----------------
__global__ void __launch_bounds__(256) gemm2_tc_kernel(
    const float* __restrict__ W,
    const float* __restrict__ att_s, const float* __restrict__ att_d, int n) {
    __shared__ float sA[128][36];
    __shared__ float sW[32][72];

    int tid = threadIdx.x;
    int warp = tid >> 5, lane = tid & 31;
    int gid = lane >> 2, tig = lane & 3;
    int row0 = blockIdx.x * 128;

    float acc[8][4];
#pragma unroll
    for (int nt = 0; nt < 8; nt++)
#pragma unroll
        for (int r = 0; r < 4; r++) acc[nt][r] = 0.f;

    for (int kc = 0; kc < 4; kc++) {
        int k0 = kc * 32;
        __syncthreads();
#pragma unroll
        for (int rep = 0; rep < 4; rep++) {
            int f = tid + rep * 256;
            int r = f >> 3, c4 = f & 7;
            int gr = row0 + r;
            float4 v = make_float4(0.f, 0.f, 0.f, 0.f);
            if (gr < n) v = *(const float4*)&g_acc[gr * 128 + k0 + c4 * 4];
            float4 t = make_float4(f2tf32(v.x), f2tf32(v.y), f2tf32(v.z), f2tf32(v.w));
            *(float4*)&sA[r][c4 * 4] = t;
        }
#pragma unroll
        for (int rep = 0; rep < 2; rep++) {
            int f = tid + rep * 256;
            int kr = f >> 4, c4 = f & 15;
            float4 v = *(const float4*)&W[(k0 + kr) * 64 + c4 * 4];
            float4 t = make_float4(f2tf32(v.x), f2tf32(v.y), f2tf32(v.z), f2tf32(v.w));
            *(float4*)&sW[kr][c4 * 4] = t;
        }
        __syncthreads();
#pragma unroll
        for (int ks = 0; ks < 4; ks++) {
            int kk = ks * 8;
            unsigned a[4], b[8][2];
            {
                int r = warp * 16 + gid;
                a[0] = __float_as_uint(sA[r][kk + tig]);
                a[1] = __float_as_uint(sA[r + 8][kk + tig]);
                a[2] = __float_as_uint(sA[r][kk + tig + 4]);
                a[3] = __float_as_uint(sA[r + 8][kk + tig + 4]);
            }
#pragma unroll
            for (int nt = 0; nt < 8; nt++) {
                int c = nt * 8 + gid;
                b[nt][0] = __float_as_uint(sW[kk + tig][c]);
                b[nt][1] = __float_as_uint(sW[kk + tig + 4][c]);
            }
#pragma unroll
            for (int nt = 0; nt < 8; nt++) mma_tf32(acc[nt], a, b[nt]);
        }
    }

    float asr[16], adr[16];
#pragma unroll
    for (int nt = 0; nt < 8; nt++) {
        int c = nt * 8 + tig * 2;
        asr[nt * 2 + 0] = att_s[c];
        asr[nt * 2 + 1] = att_s[c + 1];
        adr[nt * 2 + 0] = att_d[c];
        adr[nt * 2 + 1] = att_d[c + 1];
    }
    float mxs = __int_as_float(0xff800000), mxd = __int_as_float(0xff800000);
#pragma unroll
    for (int half = 0; half < 2; half++) {
        int r = row0 + warp * 16 + gid + half * 8;
        float sa = 0.f, sd = 0.f;
        if (r < n) {
#pragma unroll
            for (int nt = 0; nt < 8; nt++) {
                float c0 = acc[nt][half * 2 + 0];
                float c1 = acc[nt][half * 2 + 1];
                int col = nt * 8 + tig * 2;
                *(__half2*)&g_h1h[r * 64 + col] =
                    __float22half2_rn(make_float2(c0, c1));
                sa += c0 * asr[nt * 2] + c1 * asr[nt * 2 + 1];
                sd += c0 * adr[nt * 2] + c1 * adr[nt * 2 + 1];
            }
        }
        sa += __shfl_xor_sync(0xffffffffu, sa, 1);
        sa += __shfl_xor_sync(0xffffffffu, sa, 2);
        sd += __shfl_xor_sync(0xffffffffu, sd, 1);
        sd += __shfl_xor_sync(0xffffffffu, sd, 2);
        if (r < n) {
            mxs = fmaxf(mxs, sa);
            mxd = fmaxf(mxd, sd);
            if (tig == 0) {
                g_as2[r] = sa;
                g_ad2[r] = sd;
            }
        }
    }
#pragma unroll
    for (int off = 16; off > 0; off >>= 1) {
        mxs = fmaxf(mxs, __shfl_xor_sync(0xffffffffu, mxs, off));
        mxd = fmaxf(mxd, __shfl_xor_sync(0xffffffffu, mxd, off));
    }
    if (lane == 0) {
        atomicMaxF(&g_gmax2[0], mxs);
        atomicMaxF(&g_gmax2[1], mxd);
    }
}

// ---------------- [8] layer 2 gather (warp/dst), fp16 h, unroll 8/4/1 ----------------
__global__ void gat2_gather_kernel(float* __restrict__ out,
                                   const float* __restrict__ b2,
                                   const float* __restrict__ gamma,
                                   const float* __restrict__ beta,
                                   const float* __restrict__ mean,
                                   const float* __restrict__ var, int n) {
    int w = (blockIdx.x * blockDim.x + threadIdx.x) >> 5;
    int lane = threadIdx.x & 31;
    if (w >= n) return;
    int beg = g_row[w], end = g_row[w + 1];
    float ad = g_ad2[w];
    float ub = lrelu(g_gmax2[0] + g_gmax2[1]);

    float2 acc = make_float2(0.f, 0.f);
    float ssum = 0.f;
    int cb = lane * 2;
    int e = beg;
    for (; e + 8 <= end; e += 8) {
        int sv[8];
#pragma unroll
        for (int j = 0; j < 8; j++) sv[j] = g_csrc[e + j];
        float av[8];
#pragma unroll
        for (int j = 0; j < 8; j++) av[j] = g_as2[sv[j]];
        unsigned hv[8];
#pragma unroll
        for (int j = 0; j < 8; j++) hv[j] = *(const unsigned*)&g_h1h[sv[j] * 64 + cb];
#pragma unroll
        for (int j = 0; j < 8; j++) {
            float p = __expf(lrelu(av[j] + ad) - ub);
            ssum += p;
            float2 f = __half22float2(*(__half2*)&hv[j]);
            acc.x += p * f.x;
            acc.y += p * f.y;
        }
    }
    for (; e + 4 <= end; e += 4) {
        int sv[4];
#pragma unroll
        for (int j = 0; j < 4; j++) sv[j] = g_csrc[e + j];
        float av[4];
#pragma unroll
        for (int j = 0; j < 4; j++) av[j] = g_as2[sv[j]];
        unsigned hv[4];
#pragma unroll
        for (int j = 0; j < 4; j++) hv[j] = *(const unsigned*)&g_h1h[sv[j] * 64 + cb];
#pragma unroll
        for (int j = 0; j < 4; j++) {
            float p = __expf(lrelu(av[j] + ad) - ub);
            ssum += p;
            float2 f = __half22float2(*(__half2*)&hv[j]);
            acc.x += p * f.x;
            acc.y += p * f.y;
        }
    }
    for (; e < end; e++) {
        int s0 = g_csrc[e];
        float a0 = g_as2[s0];
        unsigned v0 = *(const unsigned*)&g_h1h[s0 * 64 + cb];
        float p0 = __expf(lrelu(a0 + ad) - ub);
        ssum += p0;
        float2 f = __half22float2(*(__half2*)&v0);
        acc.x += p0 * f.x;
        acc.y += p0 * f.y;
    }

    float inv = 1.f / ssum;
    float vx = acc.x * inv + b2[cb];
    float vy = acc.y * inv + b2[cb + 1];
    vx = gamma[cb] * (vx - mean[cb]) * rsqrtf(var[cb] + EPS_BN) + beta[cb];
    vy = gamma[cb + 1] * (vy - mean[cb + 1]) * rsqrtf(var[cb + 1] + EPS_BN) + beta[cb + 1];
    *(float2*)&out[w * 64 + cb] = make_float2(vx, vy);
}

// ---------------- launcher ----------------
extern "C" void kernel_launch(void* const* d_in, const int* in_sizes, int n_in,
                              void* d_out, int out_size) {
    const float* x        = (const float*)d_in[0];
    const int*   ei       = (const int*)d_in[1];   // int32 (JAX demotes int64)
    const float* W1       = (const float*)d_in[2];
    const float* att_src1 = (const float*)d_in[3];
    const float* att_dst1 = (const float*)d_in[4];
    const float* b1       = (const float*)d_in[5];
    const float* bn1_g    = (const float*)d_in[6];
    const float* bn1_b    = (const float*)d_in[7];
    const float* bn1_m    = (const float*)d_in[8];
    const float* bn1_v    = (const float*)d_in[9];
    const float* W2       = (const float*)d_in[10];
    const float* att_src2 = (const float*)d_in[11];
    const float* att_dst2 = (const float*)d_in[12];
    const float* b2       = (const float*)d_in[13];
    const float* bn2_g    = (const float*)d_in[14];
    const float* bn2_b    = (const float*)d_in[15];
    const float* bn2_m    = (const float*)d_in[16];
    const float* bn2_v    = (const float*)d_in[17];
    float* out = (float*)d_out;

    int n = in_sizes[0] / 128;
    int E = in_sizes[1] / 2;
    int ET = E + n;
    int nb = (n + SCAN_CHUNK - 1) / SCAN_CHUNK;

    const int B = 256;

    // [1] histogram (+ gmax init; relies on g_cnt==0 invariant)
    hist_kernel<<<(ET + B - 1) / B, B>>>(ei, E, n);
    // [2][3] scan (scan_down re-zeroes g_cnt for next replay)
    scan_part_kernel<<<nb, 256>>>(n);
    scan_down_kernel<<<nb, 256>>>(n, nb);
    // [4] scatter
    scatter_kernel<<<(ET + B - 1) / B, B>>>(ei, E, n);
    // [5] layer 1 GEMM + scores + gmax
    gemm1_tc_kernel<<<(n + 127) / 128, 256>>>(x, W1, att_src1, att_dst1, n);
    // [6] layer 1 gather  (launch #6 -> gets profiled by ncu -s 5 -c 1)
    gat1_gather_kernel<<<(n * 32 + B - 1) / B, B>>>(b1, bn1_g, bn1_b, bn1_m, bn1_v, n);
    // [7] layer 2 GEMM + scores + gmax (h2 -> fp16)
    gemm2_tc_kernel<<<(n + 127) / 128, 256>>>(W2, att_src2, att_dst2, n);
    // [8] layer 2 gather
    gat2_gather_kernel<<<(n * 32 + B - 1) / B, B>>>(out, b2, bn2_g, bn2_b, bn2_m, bn2_v, n);
}

// round 10
// speedup vs baseline: 4.5148x; 1.0387x over previous
#include <cuda_runtime.h>
#include <cuda_fp16.h>

#define NMAX 100000
#define EMAX 1600000
#define ETMAX (EMAX + NMAX)
#define SCAN_CHUNK 1024
#define SCAN_BLOCKS ((NMAX + SCAN_CHUNK - 1) / SCAN_CHUNK)

// ---------------- scratch (static device globals; no allocation) ----------------
__device__ __align__(16) float g_h1[NMAX * 128];    // (spare fp32 scratch)
__device__ __align__(16) __half g_h1h[NMAX * 128];  // layer1 h fp16; reused for layer2 h fp16 (stride 64)
__device__ __align__(16) float g_acc[NMAX * 128];   // layer1 output (post BN/ReLU)
__device__ __align__(16) float g_as1[NMAX * 4];
__device__ __align__(16) float g_ad1[NMAX * 4];
__device__ __align__(16) float g_as2[NMAX];
__device__ __align__(16) float g_ad2[NMAX];
__device__ float g_gmax[8];    // [0..3]=max as1 per head, [4..7]=max ad1 per head
__device__ float g_gmax2[2];   // [0]=max as2, [1]=max ad2
__device__ int g_cnt[NMAX];    // INVARIANT: zero on entry (re-zeroed by scan_down)
__device__ int g_row[NMAX + 1];
__device__ int g_cur[NMAX];
__device__ int g_csrc[ETMAX];
__device__ int g_part[SCAN_BLOCKS + 1];

#define NEG_SLOPE 0.2f
#define EPS_BN 1e-5f

__device__ __forceinline__ float lrelu(float v) {
    return v > 0.f ? v : NEG_SLOPE * v;
}

__device__ __forceinline__ void atomicMaxF(float* addr, float v) {
    if (v >= 0.f) atomicMax((int*)addr, __float_as_int(v));
    else          atomicMin((unsigned int*)addr, __float_as_uint(v));
}

__device__ __forceinline__ float f2tf32(float f) {
    unsigned u;
    asm("cvt.rna.tf32.f32 %0, %1;" : "=r"(u) : "f"(f));
    return __uint_as_float(u);
}

__device__ __forceinline__ void mma_tf32(float* c, const unsigned* a, const unsigned* b) {
    asm volatile(
        "mma.sync.aligned.m16n8k8.row.col.f32.tf32.tf32.f32 "
        "{%0,%1,%2,%3}, {%4,%5,%6,%7}, {%8,%9}, {%0,%1,%2,%3};\n"
        : "+f"(c[0]), "+f"(c[1]), "+f"(c[2]), "+f"(c[3])
        : "r"(a[0]), "r"(a[1]), "r"(a[2]), "r"(a[3]), "r"(b[0]), "r"(b[1]));
}

// ---------------- [side 1] histogram over dst (E real edges only) + gmax init ----------------
__global__ void hist_kernel(const int* __restrict__ ei, int E) {
    if (blockIdx.x == 0 && threadIdx.x < 10) {
        float ninf = __int_as_float(0xff800000);
        if (threadIdx.x < 8) g_gmax[threadIdx.x] = ninf;
        else                 g_gmax2[threadIdx.x - 8] = ninf;
    }
    int e = blockIdx.x * blockDim.x + threadIdx.x;
    if (e >= E) return;
    atomicAdd(&g_cnt[__ldg(&ei[E + e])], 1);
}

// ---------------- [side 2] per-block partial sums (+1 self-loop per node) ----------------
__global__ void scan_part_kernel(int n) {
    __shared__ int sh[256];
    int blk = blockIdx.x;
    int t = threadIdx.x;
    int base = blk * SCAN_CHUNK + t * 4;
    int s = 0;
#pragma unroll
    for (int i = 0; i < 4; i++) {
        int idx = base + i;
        if (idx < n) s += g_cnt[idx] + 1;   // +1 = self-loop
    }
    sh[t] = s;
    __syncthreads();
#pragma unroll
    for (int off = 128; off > 0; off >>= 1) {
        if (t < off) sh[t] += sh[t + off];
        __syncthreads();
    }
    if (t == 0) g_part[blk] = sh[0];
}

// ---------------- [side 3] down-sweep: top scan + local scan + self-loop write + re-zero ----------------
__global__ void scan_down_kernel(int n, int nb) {
    __shared__ int sp[128];
    __shared__ int sh[256];
    int blk = blockIdx.x;
    int t = threadIdx.x;

    if (t < 128) sp[t] = (t < nb) ? g_part[t] : 0;
    __syncthreads();
    for (int off = 1; off < 128; off <<= 1) {
        int u = 0;
        if (t < 128 && t >= off) u = sp[t - off];
        __syncthreads();
        if (t < 128) sp[t] += u;
        __syncthreads();
    }
    if (blk == 0 && t == 0) g_row[n] = sp[nb - 1];
    int blockoff = sp[blk] - g_part[blk];

    int base = blk * SCAN_CHUNK + t * 4;
    int v[4];
    int s = 0;
#pragma unroll
    for (int i = 0; i < 4; i++) {
        int idx = base + i;
        v[i] = (idx < n) ? (g_cnt[idx] + 1) : 0;
        s += v[i];
    }
    sh[t] = s;
    __syncthreads();
    for (int off = 1; off < 256; off <<= 1) {
        int u = (t >= off) ? sh[t - off] : 0;
        __syncthreads();
        sh[t] += u;
        __syncthreads();
    }
    int running = sh[t] - s + blockoff;
#pragma unroll
    for (int i = 0; i < 4; i++) {
        int idx = base + i;
        if (idx < n) {
            g_row[idx] = running;
            g_csrc[running] = idx;       // self-loop src at row start
            g_cur[idx] = running + 1;    // real edges start after it
            g_cnt[idx] = 0;              // restore invariant for next replay
            running += v[i];
        }
    }
}

// ---------------- [side 4] scatter src by dst (E real edges only) ----------------
__global__ void scatter_kernel(const int* __restrict__ ei, int E) {
    int e = blockIdx.x * blockDim.x + threadIdx.x;
    if (e >= E) return;
    int src = __ldg(&ei[e]);
    int dst = __ldg(&ei[E + e]);
    int pos = atomicAdd(&g_cur[dst], 1);
    g_csrc[pos] = src;
}

// ---------------- [main 1] layer 1 GEMM (tensor core, tf32) + fused scores + gmax ----------------
__global__ void __launch_bounds__(256) gemm1_tc_kernel(
    const float* __restrict__ A, const float* __restrict__ W,
    const float* __restrict__ att_s, const float* __restrict__ att_d, int n) {
    __shared__ float sA[128][36];
    __shared__ float sW[32][136];

    int tid = threadIdx.x;
    int warp = tid >> 5, lane = tid & 31;
    int gid = lane >> 2, tig = lane & 3;
    int mwarp = warp >> 2, nwarp = warp & 3;
    int row0 = blockIdx.x * 128;

    float acc[4][4][4];
#pragma unroll
    for (int mt = 0; mt < 4; mt++)
#pragma unroll
        for (int nt = 0; nt < 4; nt++)
#pragma unroll
            for (int r = 0; r < 4; r++) acc[mt][nt][r] = 0.f;

    for (int kc = 0; kc < 4; kc++) {
        int k0 = kc * 32;
        __syncthreads();
#pragma unroll
        for (int rep = 0; rep < 4; rep++) {
            int f = tid + rep * 256;
            int r = f >> 3, c4 = f & 7;
            int gr = row0 + r;
            float4 v = make_float4(0.f, 0.f, 0.f, 0.f);
            if (gr < n) v = *(const float4*)&A[gr * 128 + k0 + c4 * 4];
            float4 t = make_float4(f2tf32(v.x), f2tf32(v.y), f2tf32(v.z), f2tf32(v.w));
            *(float4*)&sA[r][c4 * 4] = t;
        }
#pragma unroll
        for (int rep = 0; rep < 4; rep++) {
            int f = tid + rep * 256;
            int kr = f >> 5, c4 = f & 31;
            float4 v = *(const float4*)&W[(k0 + kr) * 128 + c4 * 4];
            float4 t = make_float4(f2tf32(v.x), f2tf32(v.y), f2tf32(v.z), f2tf32(v.w));
            *(float4*)&sW[kr][c4 * 4] = t;
        }
        __syncthreads();
#pragma unroll
        for (int ks = 0; ks < 4; ks++) {
            int kk = ks * 8;
            unsigned b[4][2], a[4][4];
#pragma unroll
            for (int nt = 0; nt < 4; nt++) {
                int c = nwarp * 32 + nt * 8 + gid;
                b[nt][0] = __float_as_uint(sW[kk + tig][c]);
                b[nt][1] = __float_as_uint(sW[kk + tig + 4][c]);
            }
#pragma unroll
            for (int mt = 0; mt < 4; mt++) {
                int r = mwarp * 64 + mt * 16 + gid;
                a[mt][0] = __float_as_uint(sA[r][kk + tig]);
                a[mt][1] = __float_as_uint(sA[r + 8][kk + tig]);
                a[mt][2] = __float_as_uint(sA[r][kk + tig + 4]);
                a[mt][3] = __float_as_uint(sA[r + 8][kk + tig + 4]);
            }
#pragma unroll
            for (int mt = 0; mt < 4; mt++)
#pragma unroll
                for (int nt = 0; nt < 4; nt++) mma_tf32(acc[mt][nt], a[mt], b[nt]);
        }
    }

    float asr[8], adr[8];
#pragma unroll
    for (int nt = 0; nt < 4; nt++) {
        int c = nwarp * 32 + nt * 8 + tig * 2;
        asr[nt * 2 + 0] = att_s[c];
        asr[nt * 2 + 1] = att_s[c + 1];
        adr[nt * 2 + 0] = att_d[c];
        adr[nt * 2 + 1] = att_d[c + 1];
    }
    float mxs = __int_as_float(0xff800000), mxd = __int_as_float(0xff800000);
#pragma unroll
    for (int mt = 0; mt < 4; mt++) {
#pragma unroll
        for (int half = 0; half < 2; half++) {
            int r = row0 + mwarp * 64 + mt * 16 + gid + half * 8;
            float sa = 0.f, sd = 0.f;
            if (r < n) {
#pragma unroll
                for (int nt = 0; nt < 4; nt++) {
                    float c0 = acc[mt][nt][half * 2 + 0];
                    float c1 = acc[mt][nt][half * 2 + 1];
                    int col = nwarp * 32 + nt * 8 + tig * 2;
                    *(__half2*)&g_h1h[r * 128 + col] =
                        __float22half2_rn(make_float2(c0, c1));
                    sa += c0 * asr[nt * 2] + c1 * asr[nt * 2 + 1];
                    sd += c0 * adr[nt * 2] + c1 * adr[nt * 2 + 1];
                }
            }
            sa += __shfl_xor_sync(0xffffffffu, sa, 1);
            sa += __shfl_xor_sync(0xffffffffu, sa, 2);
            sd += __shfl_xor_sync(0xffffffffu, sd, 1);
            sd += __shfl_xor_sync(0xffffffffu, sd, 2);
            if (r < n) {
                mxs = fmaxf(mxs, sa);
                mxd = fmaxf(mxd, sd);
                if (tig == 0) {
                    g_as1[r * 4 + nwarp] = sa;
                    g_ad1[r * 4 + nwarp] = sd;
                }
            }
        }
    }
#pragma unroll
    for (int off = 16; off > 0; off >>= 1) {
        mxs = fmaxf(mxs, __shfl_xor_sync(0xffffffffu, mxs, off));
        mxd = fmaxf(mxd, __shfl_xor_sync(0xffffffffu, mxd, off));
    }
    if (lane == 0) {
        atomicMaxF(&g_gmax[nwarp], mxs);
        atomicMaxF(&g_gmax[4 + nwarp], mxd);
    }
}

// ---------------- [main 2] layer 1 gather (warp/dst), global-ub softmax ----------------
__global__ void gat1_gather_kernel(const float* __restrict__ b1,
                                   const float* __restrict__ gamma,
                                   const float* __restrict__ beta,
                                   const float* __restrict__ mean,
                                   const float* __restrict__ var, int n) {
    int w = (blockIdx.x * blockDim.x + threadIdx.x) >> 5;
    int lane = threadIdx.x & 31;
    if (w >= n) return;
    int h = lane >> 3;
    int beg = g_row[w], end = g_row[w + 1];
    float ad = g_ad1[w * 4 + h];
    float ub = lrelu(g_gmax[h] + g_gmax[4 + h]);

    float4 acc = make_float4(0.f, 0.f, 0.f, 0.f);
    float ssum = 0.f;
    int cb = lane * 4;
    int e = beg;
    for (; e + 8 <= end; e += 8) {
        int sv[8];
#pragma unroll
        for (int j = 0; j < 8; j++) sv[j] = __ldg(&g_csrc[e + j]);
        float av[8];
#pragma unroll
        for (int j = 0; j < 8; j++) av[j] = __ldg(&g_as1[sv[j] * 4 + h]);
        uint2 hv[8];
#pragma unroll
        for (int j = 0; j < 8; j++) hv[j] = __ldg((const uint2*)&g_h1h[sv[j] * 128 + cb]);
#pragma unroll
        for (int j = 0; j < 8; j++) {
            float p = __expf(lrelu(av[j] + ad) - ub);
            ssum += p;
            float2 f01 = __half22float2(*(__half2*)&hv[j].x);
            float2 f23 = __half22float2(*(__half2*)&hv[j].y);
            acc.x += p * f01.x;
            acc.y += p * f01.y;
            acc.z += p * f23.x;
            acc.w += p * f23.y;
        }
    }
    for (; e + 4 <= end; e += 4) {
        int sv[4];
#pragma unroll
        for (int j = 0; j < 4; j++) sv[j] = __ldg(&g_csrc[e + j]);
        float av[4];
#pragma unroll
        for (int j = 0; j < 4; j++) av[j] = __ldg(&g_as1[sv[j] * 4 + h]);
        uint2 hv[4];
#pragma unroll
        for (int j = 0; j < 4; j++) hv[j] = __ldg((const uint2*)&g_h1h[sv[j] * 128 + cb]);
#pragma unroll
        for (int j = 0; j < 4; j++) {
            float p = __expf(lrelu(av[j] + ad) - ub);
            ssum += p;
            float2 f01 = __half22float2(*(__half2*)&hv[j].x);
            float2 f23 = __half22float2(*(__half2*)&hv[j].y);
            acc.x += p * f01.x;
            acc.y += p * f01.y;
            acc.z += p * f23.x;
            acc.w += p * f23.y;
        }
    }
    for (; e < end; e++) {
        int s0 = __ldg(&g_csrc[e]);
        float a0 = __ldg(&g_as1[s0 * 4 + h]);
        uint2 v0 = __ldg((const uint2*)&g_h1h[s0 * 128 + cb]);
        float p0 = __expf(lrelu(a0 + ad) - ub);
        ssum += p0;
        float2 f01 = __half22float2(*(__half2*)&v0.x);
        float2 f23 = __half22float2(*(__half2*)&v0.y);
        acc.x += p0 * f01.x;
        acc.y += p0 * f01.y;
        acc.z += p0 * f23.x;
        acc.w += p0 * f23.y;
    }

    float inv = 1.f / ssum;
    float4 o;
#pragma unroll
    for (int j = 0; j < 4; j++) {
        float v = ((&acc.x)[j]) * inv + b1[cb + j];
        v = gamma[cb + j] * (v - mean[cb + j]) * rsqrtf(var[cb + j] + EPS_BN) + beta[cb + j];
        (&o.x)[j] = fmaxf(v, 0.f);
    }
    *(float4*)&g_acc[w * 128 + cb] = o;
}

// ---------------- [main 3] layer 2 GEMM (tensor core, tf32): h2 -> fp16, scores, gmax ----------------
__global__ void __launch_bounds__(256) gemm2_tc_kernel(
    const float* __restrict__ W,
    const float* __restrict__ att_s, const float* __restrict__ att_d, int n) {
    __shared__ float sA[128][36];
    __shared__ float sW[32][72];

    int tid = threadIdx.x;
    int warp = tid >> 5, lane = tid & 31;
    int gid = lane >> 2, tig = lane & 3;
    int row0 = blockIdx.x * 128;

    float acc[8][4];
#pragma unroll
    for (int nt = 0; nt < 8; nt++)
#pragma unroll
        for (int r = 0; r < 4; r++) acc[nt][r] = 0.f;

    for (int kc = 0; kc < 4; kc++) {
        int k0 = kc * 32;
        __syncthreads();
#pragma unroll
        for (int rep = 0; rep < 4; rep++) {
            int f = tid + rep * 256;
            int r = f >> 3, c4 = f & 7;
            int gr = row0 + r;
            float4 v = make_float4(0.f, 0.f, 0.f, 0.f);
            if (gr < n) v = *(const float4*)&g_acc[gr * 128 + k0 + c4 * 4];
            float4 t = make_float4(f2tf32(v.x), f2tf32(v.y), f2tf32(v.z), f2tf32(v.w));
            *(float4*)&sA[r][c4 * 4] = t;
        }
#pragma unroll
        for (int rep = 0; rep < 2; rep++) {
            int f = tid + rep * 256;
            int kr = f >> 4, c4 = f & 15;
            float4 v = *(const float4*)&W[(k0 + kr) * 64 + c4 * 4];
            float4 t = make_float4(f2tf32(v.x), f2tf32(v.y), f2tf32(v.z), f2tf32(v.w));
            *(float4*)&sW[kr][c4 * 4] = t;
        }
        __syncthreads();
#pragma unroll
        for (int ks = 0; ks < 4; ks++) {
            int kk = ks * 8;
            unsigned a[4], b[8][2];
            {
                int r = warp * 16 + gid;
                a[0] = __float_as_uint(sA[r][kk + tig]);
                a[1] = __float_as_uint(sA[r + 8][kk + tig]);
                a[2] = __float_as_uint(sA[r][kk + tig + 4]);
                a[3] = __float_as_uint(sA[r + 8][kk + tig + 4]);
            }
#pragma unroll
            for (int nt = 0; nt < 8; nt++) {
                int c = nt * 8 + gid;
                b[nt][0] = __float_as_uint(sW[kk + tig][c]);
                b[nt][1] = __float_as_uint(sW[kk + tig + 4][c]);
            }
#pragma unroll
            for (int nt = 0; nt < 8; nt++) mma_tf32(acc[nt], a, b[nt]);
        }
    }

    float asr[16], adr[16];
#pragma unroll
    for (int nt = 0; nt < 8; nt++) {
        int c = nt * 8 + tig * 2;
        asr[nt * 2 + 0] = att_s[c];
        asr[nt * 2 + 1] = att_s[c + 1];
        adr[nt * 2 + 0] = att_d[c];
        adr[nt * 2 + 1] = att_d[c + 1];
    }
    float mxs = __int_as_float(0xff800000), mxd = __int_as_float(0xff800000);
#pragma unroll
    for (int half = 0; half < 2; half++) {
        int r = row0 + warp * 16 + gid + half * 8;
        float sa = 0.f, sd = 0.f;
        if (r < n) {
#pragma unroll
            for (int nt = 0; nt < 8; nt++) {
                float c0 = acc[nt][half * 2 + 0];
                float c1 = acc[nt][half * 2 + 1];
                int col = nt * 8 + tig * 2;
                *(__half2*)&g_h1h[r * 64 + col] =
                    __float22half2_rn(make_float2(c0, c1));
                sa += c0 * asr[nt * 2] + c1 * asr[nt * 2 + 1];
                sd += c0 * adr[nt * 2] + c1 * adr[nt * 2 + 1];
            }
        }
        sa += __shfl_xor_sync(0xffffffffu, sa, 1);
        sa += __shfl_xor_sync(0xffffffffu, sa, 2);
        sd += __shfl_xor_sync(0xffffffffu, sd, 1);
        sd += __shfl_xor_sync(0xffffffffu, sd, 2);
        if (r < n) {
            mxs = fmaxf(mxs, sa);
            mxd = fmaxf(mxd, sd);
            if (tig == 0) {
                g_as2[r] = sa;
                g_ad2[r] = sd;
            }
        }
    }
#pragma unroll
    for (int off = 16; off > 0; off >>= 1) {
        mxs = fmaxf(mxs, __shfl_xor_sync(0xffffffffu, mxs, off));
        mxd = fmaxf(mxd, __shfl_xor_sync(0xffffffffu, mxd, off));
    }
    if (lane == 0) {
        atomicMaxF(&g_gmax2[0], mxs);
        atomicMaxF(&g_gmax2[1], mxd);
    }
}

// ---------------- [main 4] layer 2 gather (warp/dst), fp16 h ----------------
__global__ void gat2_gather_kernel(float* __restrict__ out,
                                   const float* __restrict__ b2,
                                   const float* __restrict__ gamma,
                                   const float* __restrict__ beta,
                                   const float* __restrict__ mean,
                                   const float* __restrict__ var, int n) {
    int w = (blockIdx.x * blockDim.x + threadIdx.x) >> 5;
    int lane = threadIdx.x & 31;
    if (w >= n) return;
    int beg = g_row[w], end = g_row[w + 1];
    float ad = g_ad2[w];
    float ub = lrelu(g_gmax2[0] + g_gmax2[1]);

    float2 acc = make_float2(0.f, 0.f);
    float ssum = 0.f;
    int cb = lane * 2;
    int e = beg;
    for (; e + 8 <= end; e += 8) {
        int sv[8];
#pragma unroll
        for (int j = 0; j < 8; j++) sv[j] = __ldg(&g_csrc[e + j]);
        float av[8];
#pragma unroll
        for (int j = 0; j < 8; j++) av[j] = __ldg(&g_as2[sv[j]]);
        unsigned hv[8];
#pragma unroll
        for (int j = 0; j < 8; j++) hv[j] = __ldg((const unsigned*)&g_h1h[sv[j] * 64 + cb]);
#pragma unroll
        for (int j = 0; j < 8; j++) {
            float p = __expf(lrelu(av[j] + ad) - ub);
            ssum += p;
            float2 f = __half22float2(*(__half2*)&hv[j]);
            acc.x += p * f.x;
            acc.y += p * f.y;
        }
    }
    for (; e + 4 <= end; e += 4) {
        int sv[4];
#pragma unroll
        for (int j = 0; j < 4; j++) sv[j] = __ldg(&g_csrc[e + j]);
        float av[4];
#pragma unroll
        for (int j = 0; j < 4; j++) av[j] = __ldg(&g_as2[sv[j]]);
        unsigned hv[4];
#pragma unroll
        for (int j = 0; j < 4; j++) hv[j] = __ldg((const unsigned*)&g_h1h[sv[j] * 64 + cb]);
#pragma unroll
        for (int j = 0; j < 4; j++) {
            float p = __expf(lrelu(av[j] + ad) - ub);
            ssum += p;
            float2 f = __half22float2(*(__half2*)&hv[j]);
            acc.x += p * f.x;
            acc.y += p * f.y;
        }
    }
    for (; e < end; e++) {
        int s0 = __ldg(&g_csrc[e]);
        float a0 = __ldg(&g_as2[s0]);
        unsigned v0 = __ldg((const unsigned*)&g_h1h[s0 * 64 + cb]);
        float p0 = __expf(lrelu(a0 + ad) - ub);
        ssum += p0;
        float2 f = __half22float2(*(__half2*)&v0);
        acc.x += p0 * f.x;
        acc.y += p0 * f.y;
    }

    float inv = 1.f / ssum;
    float vx = acc.x * inv + b2[cb];
    float vy = acc.y * inv + b2[cb + 1];
    vx = gamma[cb] * (vx - mean[cb]) * rsqrtf(var[cb] + EPS_BN) + beta[cb];
    vy = gamma[cb + 1] * (vy - mean[cb + 1]) * rsqrtf(var[cb + 1] + EPS_BN) + beta[cb + 1];
    *(float2*)&out[w * 64 + cb] = make_float2(vx, vy);
}

// ---------------- launcher: fork CSR chain || gemm1 ----------------
extern "C" void kernel_launch(void* const* d_in, const int* in_sizes, int n_in,
                              void* d_out, int out_size) {
    const float* x        = (const float*)d_in[0];
    const int*   ei       = (const int*)d_in[1];   // int32 (JAX demotes int64)
    const float* W1       = (const float*)d_in[2];
    const float* att_src1 = (const float*)d_in[3];
    const float* att_dst1 = (const float*)d_in[4];
    const float* b1       = (const float*)d_in[5];
    const float* bn1_g    = (const float*)d_in[6];
    const float* bn1_b    = (const float*)d_in[7];
    const float* bn1_m    = (const float*)d_in[8];
    const float* bn1_v    = (const float*)d_in[9];
    const float* W2       = (const float*)d_in[10];
    const float* att_src2 = (const float*)d_in[11];
    const float* att_dst2 = (const float*)d_in[12];
    const float* b2       = (const float*)d_in[13];
    const float* bn2_g    = (const float*)d_in[14];
    const float* bn2_b    = (const float*)d_in[15];
    const float* bn2_m    = (const float*)d_in[16];
    const float* bn2_v    = (const float*)d_in[17];
    float* out = (float*)d_out;

    int n = in_sizes[0] / 128;
    int E = in_sizes[1] / 2;
    int nb = (n + SCAN_CHUNK - 1) / SCAN_CHUNK;

    const int B = 256;

    // one-time host-side resources (created during the correctness call, outside capture;
    // no device memory is allocated by us)
    static cudaStream_t side = nullptr;
    static cudaEvent_t evFork = nullptr, evJoin = nullptr;
    if (side == nullptr) {
        cudaStreamCreateWithFlags(&side, cudaStreamNonBlocking);
        cudaEventCreateWithFlags(&evFork, cudaEventDisableTiming);
        cudaEventCreateWithFlags(&evJoin, cudaEventDisableTiming);
    }

    // ---- fork: CSR build on side stream, gemm1 on main stream ----
    cudaEventRecord(evFork, 0);
    cudaStreamWaitEvent(side, evFork, 0);

    hist_kernel<<<(E + B - 1) / B, B, 0, side>>>(ei, E);
    scan_part_kernel<<<nb, 256, 0, side>>>(n);
    scan_down_kernel<<<nb, 256, 0, side>>>(n, nb);
    scatter_kernel<<<(E + B - 1) / B, B, 0, side>>>(ei, E);
    cudaEventRecord(evJoin, side);

    gemm1_tc_kernel<<<(n + 127) / 128, 256>>>(x, W1, att_src1, att_dst1, n);

    // ---- join, then the dependent chain ----
    cudaStreamWaitEvent(0, evJoin, 0);
    gat1_gather_kernel<<<(n * 32 + B - 1) / B, B>>>(b1, bn1_g, bn1_b, bn1_m, bn1_v, n);
    gemm2_tc_kernel<<<(n + 127) / 128, 256>>>(W2, att_src2, att_dst2, n);
    gat2_gather_kernel<<<(n * 32 + B - 1) / B, B>>>(out, b2, bn2_g, bn2_b, bn2_m, bn2_v, n);
}